// round 7
// baseline (speedup 1.0000x reference)
#include <cuda_runtime.h>
#include <math.h>

#define N_PTS  100000
#define PLANES 128
#define VEC    16
#define KOFF   27
#define NCHP   448        // padded 28*16 -> 1792B rows (128B aligned)
#define N_TILES 3125      // N_PTS / 32 (exact)

typedef unsigned long long ull;

#define FMA_F32X2(d, a, b, c) \
    asm("fma.rn.f32x2 %0, %1, %2, %3;" : "=l"(d) : "l"(a), "l"(b), "l"(c))
#define UNPACK_F32X2(lo, hi, in) \
    asm("mov.b64 {%0, %1}, %2;" : "=f"(lo), "=f"(hi) : "l"(in))
#define PACK_F32X2(out, lo, hi) \
    asm("mov.b64 %0, {%1, %2};" : "=l"(out) : "f"(lo), "f"(hi))

// Scratch (__device__ globals: allocation-free rule)
__device__ float g_y[(size_t)N_PTS * NCHP];       // 179.2 MB
__device__ float g_choice[N_PTS];
__device__ float g_vf[(size_t)N_PTS * PLANES];    // 51.2 MB
__device__ float g_A[VEC * PLANES];
__device__ float g_csum;

// ---------------------------------------------------------------------------
// Kernel 0: fold codebook into W_choice:  A[v][c], and csum = ||codebook||^2
// ---------------------------------------------------------------------------
__global__ void k_prep(const float* __restrict__ codebook,
                       const float* __restrict__ W_choice)
{
    const int c = threadIdx.x;   // 128 threads
    for (int v = 0; v < VEC; v++) {
        float s = 0.f;
#pragma unroll
        for (int j = 0; j < 8; j++) {
            const int jj = v * 8 + j;
            s = fmaf(__ldg(codebook + jj), __ldg(W_choice + jj * PLANES + c), s);
        }
        g_A[v * PLANES + c] = s;
    }
    if (c == 0) {
        float cs = 0.f;
        for (int j = 0; j < PLANES; j++) { float t = __ldg(codebook + j); cs = fmaf(t, t, cs); }
        g_csum = cs;
    }
}

// ---------------------------------------------------------------------------
// Kernel 1: dense GEMM  y[n, k*16+v] = sum_j x[n,j] * W_q[k,j,v]
// Block = 128 thr, tile 128 points x 32 cols (2 k's per stage, 14 stages;
// stage 13 pairs k=26 with a zeroed dummy k=27 writing into the NCHP pad).
// Thread tile 4 pts x 8 cols, f32x2 (j-packed) FMA.
// ---------------------------------------------------------------------------
__global__ __launch_bounds__(128) void k_ygemm(
    const float* __restrict__ x, const float* __restrict__ W_q)
{
    extern __shared__ float sm[];
    float* sX = sm;                  // 128 * 132
    float* sW = sm + PLANES * 132;   // 32 * 132  (rows = 2k x 16 v)

    const int tid = threadIdx.x;
    const int n0  = blockIdx.x * PLANES;

    // stage x tile (coalesced float4), zero-fill tail
    for (int r = 0; r < 32; r++) {
        const int id = r * 128 + tid;
        const int p = id >> 5, c4 = id & 31;
        const int n = n0 + p;
        float4 v = make_float4(0.f, 0.f, 0.f, 0.f);
        if (n < N_PTS) v = __ldg((const float4*)(x + (size_t)n * PLANES) + c4);
        *(float4*)&sX[p * 132 + c4 * 4] = v;
    }

    const int pg = tid >> 2, cg = tid & 3;     // 32 point-groups x 4 col-groups
    const float* xb = &sX[(pg * 4) * 132];
    const float* wb = &sW[(cg * 8) * 132];

    for (int ks = 0; ks < 14; ks++) {
        __syncthreads();
        // stage W rows for k = 2ks and 2ks+1 (zero if k==27): thread = col j
#pragma unroll
        for (int h = 0; h < 2; h++) {
            const int k = ks * 2 + h;
            float4 a, b, c, d;
            if (k < KOFF) {
                const float4* src = (const float4*)(W_q + (size_t)k * PLANES * VEC + tid * VEC);
                a = __ldg(src + 0); b = __ldg(src + 1);
                c = __ldg(src + 2); d = __ldg(src + 3);
            } else {
                a = b = c = d = make_float4(0.f, 0.f, 0.f, 0.f);
            }
            float* w0 = &sW[h * 16 * 132 + tid];
            w0[ 0*132] = a.x; w0[ 1*132] = a.y; w0[ 2*132] = a.z; w0[ 3*132] = a.w;
            w0[ 4*132] = b.x; w0[ 5*132] = b.y; w0[ 6*132] = b.z; w0[ 7*132] = b.w;
            w0[ 8*132] = c.x; w0[ 9*132] = c.y; w0[10*132] = c.z; w0[11*132] = c.w;
            w0[12*132] = d.x; w0[13*132] = d.y; w0[14*132] = d.z; w0[15*132] = d.w;
        }
        __syncthreads();

        ull acc[4][8];
#pragma unroll
        for (int i = 0; i < 4; i++)
#pragma unroll
            for (int t = 0; t < 8; t++) acc[i][t] = 0ull;

#pragma unroll 4
        for (int jj = 0; jj < 32; jj++) {
            ulonglong2 xv[4];
#pragma unroll
            for (int i = 0; i < 4; i++)
                xv[i] = *(const ulonglong2*)&xb[i * 132 + jj * 4];
#pragma unroll
            for (int t = 0; t < 8; t++) {
                const ulonglong2 wv = *(const ulonglong2*)&wb[t * 132 + jj * 4];
#pragma unroll
                for (int i = 0; i < 4; i++) {
                    FMA_F32X2(acc[i][t], xv[i].x, wv.x, acc[i][t]);
                    FMA_F32X2(acc[i][t], xv[i].y, wv.y, acc[i][t]);
                }
            }
        }
#pragma unroll
        for (int i = 0; i < 4; i++) {
            const int n = n0 + pg * 4 + i;
            if (n < N_PTS) {
                float o[8];
#pragma unroll
                for (int t = 0; t < 8; t++) {
                    float lo, hi; UNPACK_F32X2(lo, hi, acc[i][t]);
                    o[t] = lo + hi;
                }
                float4* dst = (float4*)(g_y + (size_t)n * NCHP + ks * 32 + cg * 8);
                dst[0] = make_float4(o[0], o[1], o[2], o[3]);
                dst[1] = make_float4(o[4], o[5], o[6], o[7]);
            }
        }
    }
}

// ---------------------------------------------------------------------------
// Kernel 2: warp-per-point. q_pre[v] = sum_k m * y[idx,k,v]; qf = relu(bn);
//           choice = sum_c relu(qf . A[:,c] + b_c)   -> g_choice
// ---------------------------------------------------------------------------
__global__ __launch_bounds__(256) void k_qchoice(
    const float* __restrict__ q_gamma, const float* __restrict__ q_beta,
    const float* __restrict__ b_choice,
    const int* __restrict__ nbr_idx, const int* __restrict__ nbr_mask)
{
    __shared__ float sA[VEC * PLANES];
    const int tid = threadIdx.x, lane = tid & 31, w = tid >> 5;
    for (int i = tid; i < VEC * PLANES / 4; i += 256)
        ((float4*)sA)[i] = __ldg((const float4*)g_A + i);
    __syncthreads();

    const int n = blockIdx.x * 8 + w;   // grid = 12500 -> exactly N_PTS warps

    int idxv = 0, mk = 0;
    if (lane < KOFF) {
        idxv = __ldg(nbr_idx  + lane * N_PTS + n);
        mk   = __ldg(nbr_mask + lane * N_PTS + n);
    }
    float acc = 0.f;
#pragma unroll
    for (int k = 0; k < KOFF; k++) {
        const int id = __shfl_sync(0xffffffffu, idxv, k);
        const int m  = __shfl_sync(0xffffffffu, mk,   k);
        float t = 0.f;
        if (m && lane < VEC) t = __ldg(g_y + (size_t)id * NCHP + k * VEC + lane);
        acc += t;
    }
    float qf = 0.f;
    if (lane < VEC) {
        qf = fmaf(acc, __ldg(q_gamma + lane), __ldg(q_beta + lane));
        qf = fmaxf(qf, 0.f);
    }
    float s0 = __ldg(b_choice + lane);
    float s1 = __ldg(b_choice + 32 + lane);
    float s2 = __ldg(b_choice + 64 + lane);
    float s3 = __ldg(b_choice + 96 + lane);
#pragma unroll
    for (int v = 0; v < VEC; v++) {
        const float qv = __shfl_sync(0xffffffffu, qf, v);
        s0 = fmaf(qv, sA[v * PLANES +      lane], s0);
        s1 = fmaf(qv, sA[v * PLANES + 32 + lane], s1);
        s2 = fmaf(qv, sA[v * PLANES + 64 + lane], s2);
        s3 = fmaf(qv, sA[v * PLANES + 96 + lane], s3);
    }
    float tsum = fmaxf(s0, 0.f) + fmaxf(s1, 0.f) + fmaxf(s2, 0.f) + fmaxf(s3, 0.f);
#pragma unroll
    for (int off = 16; off > 0; off >>= 1)
        tsum += __shfl_xor_sync(0xffffffffu, tsum, off);
    if (lane == 0) g_choice[n] = tsum;
}

// ---------------------------------------------------------------------------
// Kernel 3: v_f = relu((x@W_v)*gamma+beta) + repeat(coords@W_pos + b_pos, 8)
// Persistent blocks, tile = 32 points, thread tile 4p x 8c, f32x2 FMA.
// ---------------------------------------------------------------------------
__global__ __launch_bounds__(128) void k_vf(
    const float* __restrict__ x, const float* __restrict__ coords,
    const float* __restrict__ W_v, const float* __restrict__ v_gamma,
    const float* __restrict__ v_beta, const float* __restrict__ W_pos,
    const float* __restrict__ b_pos)
{
    extern __shared__ float sm[];
    float* sW = sm;                  // 128 * 132
    float* sX = sm + PLANES * 132;   // 32 * 132
    float* sC = sX + 32 * 132;       // 32 * 4

    const int tid = threadIdx.x;
    const int pg = tid >> 4, cg = tid & 15;

    for (int r = 0; r < 32; r++) {
        const int id = r * 128 + tid;
        const int j = id >> 5, c0 = (id & 31) * 4;
        const float4 v = __ldg((const float4*)W_v + id);
        sW[(((c0+0)&7)*16 + ((c0+0)>>3))*132 + j] = v.x;
        sW[(((c0+1)&7)*16 + ((c0+1)>>3))*132 + j] = v.y;
        sW[(((c0+2)&7)*16 + ((c0+2)>>3))*132 + j] = v.z;
        sW[(((c0+3)&7)*16 + ((c0+3)>>3))*132 + j] = v.w;
    }
    float gam[8], bet[8];
#pragma unroll
    for (int t = 0; t < 8; t++) {
        const int c = cg * 8 + t;
        gam[t] = __ldg(v_gamma + c); bet[t] = __ldg(v_beta + c);
    }
    const float wp0 = __ldg(W_pos + 0 * VEC + cg);
    const float wp1 = __ldg(W_pos + 1 * VEC + cg);
    const float wp2 = __ldg(W_pos + 2 * VEC + cg);
    const float bp  = __ldg(b_pos + cg);

    for (int tile = blockIdx.x; tile < N_TILES; tile += gridDim.x) {
        __syncthreads();
        for (int r = 0; r < 8; r++) {
            const int id = r * 128 + tid;
            const int p = id >> 5, c4 = id & 31;
            const int n = tile * 32 + p;
            *(float4*)&sX[p * 132 + c4 * 4] =
                __ldg((const float4*)(x + (size_t)n * PLANES) + c4);
        }
        if (tid < 32) {
            const int n = tile * 32 + tid;
            sC[tid*4+0] = __ldg(coords + n*3 + 0);
            sC[tid*4+1] = __ldg(coords + n*3 + 1);
            sC[tid*4+2] = __ldg(coords + n*3 + 2);
        }
        __syncthreads();

        ull acc[4][8];
#pragma unroll
        for (int i = 0; i < 4; i++)
#pragma unroll
            for (int t = 0; t < 8; t++) acc[i][t] = 0ull;

        const float* xb = &sX[(pg * 4) * 132];
        const float* wb = &sW[cg * 132];
#pragma unroll 4
        for (int jj = 0; jj < 32; jj++) {
            ulonglong2 xv[4];
#pragma unroll
            for (int i = 0; i < 4; i++)
                xv[i] = *(const ulonglong2*)&xb[i * 132 + jj * 4];
#pragma unroll
            for (int t = 0; t < 8; t++) {
                const ulonglong2 wv = *(const ulonglong2*)&wb[t * 16 * 132 + jj * 4];
#pragma unroll
                for (int i = 0; i < 4; i++) {
                    FMA_F32X2(acc[i][t], xv[i].x, wv.x, acc[i][t]);
                    FMA_F32X2(acc[i][t], xv[i].y, wv.y, acc[i][t]);
                }
            }
        }
#pragma unroll
        for (int i = 0; i < 4; i++) {
            const int p = pg * 4 + i;
            const int n = tile * 32 + p;
            const float pos = fmaf(sC[p*4+0], wp0,
                              fmaf(sC[p*4+1], wp1,
                              fmaf(sC[p*4+2], wp2, bp)));
            float o[8];
#pragma unroll
            for (int t = 0; t < 8; t++) {
                float lo, hi; UNPACK_F32X2(lo, hi, acc[i][t]);
                const float r = fmaf(lo + hi, gam[t], bet[t]);
                o[t] = fmaxf(r, 0.f) + pos;
            }
            float4* dst = (float4*)(g_vf + (size_t)n * PLANES + cg * 8);
            dst[0] = make_float4(o[0], o[1], o[2], o[3]);
            dst[1] = make_float4(o[4], o[5], o[6], o[7]);
        }
    }
}

// ---------------------------------------------------------------------------
// Kernel 4: warp-per-point softmax + v_f gather-aggregate into smem, then
//           f32x2 tile GEMM out = relu((agg@W_out)*gamma+beta) + x.
// ---------------------------------------------------------------------------
__global__ __launch_bounds__(128) void k_attn_out(
    const float* __restrict__ x, const float* __restrict__ W_out,
    const float* __restrict__ out_gamma, const float* __restrict__ out_beta,
    const int* __restrict__ nbr_idx, const int* __restrict__ nbr_mask,
    float* __restrict__ out)
{
    extern __shared__ float sm[];
    float* sW   = sm;                 // 128 * 132
    float* sAgg = sm + PLANES * 132;  // 32 * 132

    const int tid = threadIdx.x;
    const int lane = tid & 31, w = tid >> 5;
    const int pg = tid >> 4, cg = tid & 15;

    for (int r = 0; r < 32; r++) {
        const int id = r * 128 + tid;
        const int j = id >> 5, c0 = (id & 31) * 4;
        const float4 v = __ldg((const float4*)W_out + id);
        sW[(((c0+0)&7)*16 + ((c0+0)>>3))*132 + j] = v.x;
        sW[(((c0+1)&7)*16 + ((c0+1)>>3))*132 + j] = v.y;
        sW[(((c0+2)&7)*16 + ((c0+2)>>3))*132 + j] = v.z;
        sW[(((c0+3)&7)*16 + ((c0+3)>>3))*132 + j] = v.w;
    }
    float gam[8], bet[8];
#pragma unroll
    for (int t = 0; t < 8; t++) {
        const int c = cg * 8 + t;
        gam[t] = __ldg(out_gamma + c); bet[t] = __ldg(out_beta + c);
    }
    const float csum = g_csum;

    for (int tile = blockIdx.x; tile < N_TILES; tile += gridDim.x) {
        __syncthreads();
        // ---- phase A: each warp aggregates 8 points
#pragma unroll 1
        for (int pp = 0; pp < 8; pp++) {
            const int pl = w * 8 + pp;
            const int n  = tile * 32 + pl;
            const float chn = __ldg(g_choice + n);
            int idxv = 0, mk = 0;
            if (lane < KOFF) {
                idxv = __ldg(nbr_idx  + lane * N_PTS + n);
                mk   = __ldg(nbr_mask + lane * N_PTS + n);
            }
            float s = (mk != 0) ? chn * __ldg(g_choice + idxv) * csum : -3.0e38f;
            float mx = s;
#pragma unroll
            for (int off = 16; off > 0; off >>= 1)
                mx = fmaxf(mx, __shfl_xor_sync(0xffffffffu, mx, off));
            const float e = (mk != 0) ? __expf(s - mx) : 0.f;
            float den = e;
#pragma unroll
            for (int off = 16; off > 0; off >>= 1)
                den += __shfl_xor_sync(0xffffffffu, den, off);
            const float rd = 1.0f / den;

            ull accA = 0ull, accB = 0ull;
#pragma unroll
            for (int k0 = 0; k0 < KOFF; k0 += 9) {
                float wk[9]; int ik[9];
#pragma unroll
                for (int q = 0; q < 9; q++) {
                    wk[q] = __shfl_sync(0xffffffffu, e,    k0 + q);
                    ik[q] = __shfl_sync(0xffffffffu, idxv, k0 + q);
                }
                ulonglong2 t[9];
#pragma unroll
                for (int q = 0; q < 9; q++) {
                    t[q] = make_ulonglong2(0ull, 0ull);
                    if (wk[q] != 0.f)
                        t[q] = __ldg((const ulonglong2*)(g_vf + (size_t)ik[q] * PLANES) + lane);
                }
#pragma unroll
                for (int q = 0; q < 9; q++) {
                    ull wk2; PACK_F32X2(wk2, wk[q], wk[q]);
                    FMA_F32X2(accA, wk2, t[q].x, accA);
                    FMA_F32X2(accB, wk2, t[q].y, accB);
                }
            }
            float ax, ay, az, aw2;
            UNPACK_F32X2(ax, ay, accA);
            UNPACK_F32X2(az, aw2, accB);
            *(float4*)&sAgg[pl * 132 + lane * 4] =
                make_float4(ax * rd, ay * rd, az * rd, aw2 * rd);
        }
        __syncthreads();

        // ---- phase B: 32x128 @ 128x128 tile GEMM (f32x2) + epilogue
        ull acc[4][8];
#pragma unroll
        for (int i = 0; i < 4; i++)
#pragma unroll
            for (int t = 0; t < 8; t++) acc[i][t] = 0ull;

        const float* xb = &sAgg[(pg * 4) * 132];
        const float* wb = &sW[cg * 132];
#pragma unroll 4
        for (int jj = 0; jj < 32; jj++) {
            ulonglong2 xv[4];
#pragma unroll
            for (int i = 0; i < 4; i++)
                xv[i] = *(const ulonglong2*)&xb[i * 132 + jj * 4];
#pragma unroll
            for (int t = 0; t < 8; t++) {
                const ulonglong2 wv = *(const ulonglong2*)&wb[t * 16 * 132 + jj * 4];
#pragma unroll
                for (int i = 0; i < 4; i++) {
                    FMA_F32X2(acc[i][t], xv[i].x, wv.x, acc[i][t]);
                    FMA_F32X2(acc[i][t], xv[i].y, wv.y, acc[i][t]);
                }
            }
        }
#pragma unroll
        for (int i = 0; i < 4; i++) {
            const int n = tile * 32 + pg * 4 + i;
            const float4* xr = (const float4*)(x + (size_t)n * PLANES + cg * 8);
            const float4 x0 = __ldg(xr), x1 = __ldg(xr + 1);
            float o[8];
#pragma unroll
            for (int t = 0; t < 8; t++) {
                float lo, hi; UNPACK_F32X2(lo, hi, acc[i][t]);
                const float r = fmaf(lo + hi, gam[t], bet[t]);
                o[t] = fmaxf(r, 0.f);
            }
            float4* dst = (float4*)(out + (size_t)n * PLANES + cg * 8);
            dst[0] = make_float4(o[0] + x0.x, o[1] + x0.y, o[2] + x0.z, o[3] + x0.w);
            dst[1] = make_float4(o[4] + x1.x, o[5] + x1.y, o[6] + x1.z, o[7] + x1.w);
        }
    }
}

// ---------------------------------------------------------------------------
extern "C" void kernel_launch(void* const* d_in, const int* in_sizes, int n_in,
                              void* d_out, int out_size)
{
    const float* x         = (const float*)d_in[0];
    const float* coords    = (const float*)d_in[1];
    const float* W_q       = (const float*)d_in[2];
    const float* q_gamma   = (const float*)d_in[3];
    const float* q_beta    = (const float*)d_in[4];
    const float* W_v       = (const float*)d_in[5];
    const float* v_gamma   = (const float*)d_in[6];
    const float* v_beta    = (const float*)d_in[7];
    const float* codebook  = (const float*)d_in[8];
    const float* W_choice  = (const float*)d_in[9];
    const float* b_choice  = (const float*)d_in[10];
    const float* W_pos     = (const float*)d_in[11];
    const float* b_pos     = (const float*)d_in[12];
    const float* W_out     = (const float*)d_in[13];
    const float* out_gamma = (const float*)d_in[14];
    const float* out_beta  = (const float*)d_in[15];
    const int*   nbr_idx   = (const int*)d_in[16];
    const int*   nbr_mask  = (const int*)d_in[17];
    float* out = (float*)d_out;

    const int smem_y    = (PLANES * 132 + 32 * 132) * (int)sizeof(float);            // 84480
    const int smem_vf   = (PLANES * 132 + 32 * 132 + 128) * (int)sizeof(float);      // 84992
    const int smem_attn = (PLANES * 132 + 32 * 132) * (int)sizeof(float);            // 84480
    cudaFuncSetAttribute(k_ygemm,    cudaFuncAttributeMaxDynamicSharedMemorySize, smem_y);
    cudaFuncSetAttribute(k_vf,       cudaFuncAttributeMaxDynamicSharedMemorySize, smem_vf);
    cudaFuncSetAttribute(k_attn_out, cudaFuncAttributeMaxDynamicSharedMemorySize, smem_attn);

    k_prep<<<1, 128>>>(codebook, W_choice);
    k_ygemm<<<(N_PTS + 127) / 128, 128, smem_y>>>(x, W_q);
    k_vf<<<296, 128, smem_vf>>>(x, coords, W_v, v_gamma, v_beta, W_pos, b_pos);
    k_qchoice<<<N_PTS / 8, 256>>>(q_gamma, q_beta, b_choice, nbr_idx, nbr_mask);
    k_attn_out<<<296, 128, smem_attn>>>(x, W_out, out_gamma, out_beta,
                                        nbr_idx, nbr_mask, out);
}

// round 9
// speedup vs baseline: 2.1790x; 2.1790x over previous
#include <cuda_runtime.h>
#include <math.h>
#include <stdint.h>

#define N_PTS  100000
#define PLANES 128
#define VEC    16
#define KOFF   27
#define NCH    432
#define NCHP   448        // padded 28*16 -> 1792B rows (128B aligned)
#define N_TILES 3125      // N_PTS / 32 (exact)

__device__ __forceinline__ float to_tf32(float f) {
    float r;
    asm("cvt.rna.tf32.f32 %0, %1;" : "=f"(r) : "f"(f));
    return r;
}

#define MMA_TF32_16x8x8(d, a, b) \
    asm volatile( \
        "mma.sync.aligned.m16n8k8.row.col.f32.tf32.tf32.f32 " \
        "{%0,%1,%2,%3}, {%4,%5,%6,%7}, {%8,%9}, {%0,%1,%2,%3};" \
        : "+f"((d)[0]), "+f"((d)[1]), "+f"((d)[2]), "+f"((d)[3]) \
        : "r"((a)[0]), "r"((a)[1]), "r"((a)[2]), "r"((a)[3]), \
          "r"((b)[0]), "r"((b)[1]))

// Scratch (__device__ globals: allocation-free rule)
__device__ float g_y[(size_t)N_PTS * NCHP];       // 179.2 MB
__device__ float g_choice[N_PTS];
__device__ float g_vf[(size_t)N_PTS * PLANES];    // 51.2 MB
__device__ float g_A[VEC * PLANES];
__device__ float g_csum;
__device__ float g_Wt[NCHP * PLANES];             // W_q transposed [col][j], tf32-rounded

// ---------------------------------------------------------------------------
// Kernel 0a: fold codebook into W_choice:  A[v][c], and csum = ||codebook||^2
// ---------------------------------------------------------------------------
__global__ void k_prep(const float* __restrict__ codebook,
                       const float* __restrict__ W_choice)
{
    const int c = threadIdx.x;   // 128 threads
    for (int v = 0; v < VEC; v++) {
        float s = 0.f;
#pragma unroll
        for (int j = 0; j < 8; j++) {
            const int jj = v * 8 + j;
            s = fmaf(__ldg(codebook + jj), __ldg(W_choice + jj * PLANES + c), s);
        }
        g_A[v * PLANES + c] = s;
    }
    if (c == 0) {
        float cs = 0.f;
        for (int j = 0; j < PLANES; j++) { float t = __ldg(codebook + j); cs = fmaf(t, t, cs); }
        g_csum = cs;
    }
}

// ---------------------------------------------------------------------------
// Kernel 0b: W_t[col][j] = tf32(W_q[k, j, v]),  col = k*16+v (zero for k>=27)
// ---------------------------------------------------------------------------
__global__ void k_prepW(const float* __restrict__ W_q)
{
    const int col = blockIdx.x;   // 0..447
    const int j   = threadIdx.x;  // 0..127
    float v = 0.f;
    if (col < NCH) {
        const int k = col >> 4, vv = col & 15;
        v = __ldg(W_q + (size_t)k * PLANES * VEC + j * VEC + vv);
    }
    g_Wt[col * PLANES + j] = to_tf32(v);
}

// ---------------------------------------------------------------------------
// Kernel 1: tf32 mma.sync GEMM  y[n, col] = sum_j x[n,j] * W_t[col, j]
// Block = 128 thr (4 warps), M-tile 128, K = 128, N = 448 (7 tiles of 64).
// A staged once (tf32, stride-132 -> fragment loads conflict-free);
// B tile restaged per N-tile from g_Wt. Warp tile 32x64 via m16n8k8.
// ---------------------------------------------------------------------------
#define YG_SMEM ((PLANES * 132 + 64 * 132) * 4)

__global__ __launch_bounds__(128) void k_ygemm_mma(const float* __restrict__ x)
{
    extern __shared__ float sm[];
    float* sX = sm;                  // 128 * 132
    float* sB = sm + PLANES * 132;   // 64 * 132

    const int tid  = threadIdx.x;
    const int wid  = tid >> 5, lane = tid & 31;
    const int g    = lane >> 2, t4 = lane & 3;
    const int n0   = blockIdx.x * 128;

    // ---- stage A tile (tf32-rounded), coalesced float4 reads
    for (int it = 0; it < 32; it++) {
        const int id = it * 128 + tid;
        const int p = id >> 5, c4 = id & 31;
        const int n = n0 + p;
        float4 v = make_float4(0.f, 0.f, 0.f, 0.f);
        if (n < N_PTS) v = __ldg((const float4*)(x + (size_t)n * PLANES) + c4);
        v.x = to_tf32(v.x); v.y = to_tf32(v.y); v.z = to_tf32(v.z); v.w = to_tf32(v.w);
        *(float4*)&sX[p * 132 + c4 * 4] = v;
    }

    const uint32_t* uX = (const uint32_t*)sX;
    const uint32_t* uB = (const uint32_t*)sB;
    const int rb = wid * 32;   // warp's row base within tile

    for (int tile = 0; tile < 7; tile++) {
        __syncthreads();
        // ---- stage B tile: 64 cols x 128 k (already tf32 in g_Wt)
        for (int it = 0; it < 16; it++) {
            const int id = it * 128 + tid;
            const int r = id >> 5, c4 = id & 31;
            *(float4*)&sB[r * 132 + c4 * 4] =
                __ldg((const float4*)(g_Wt + (size_t)(tile * 64 + r) * PLANES) + c4);
        }
        __syncthreads();

        float acc[2][8][4];
#pragma unroll
        for (int mf = 0; mf < 2; mf++)
#pragma unroll
            for (int nf = 0; nf < 8; nf++)
#pragma unroll
                for (int q = 0; q < 4; q++) acc[mf][nf][q] = 0.f;

#pragma unroll 2
        for (int kb = 0; kb < 16; kb++) {
            const int k0 = kb * 8;
            uint32_t a[2][4];
#pragma unroll
            for (int mf = 0; mf < 2; mf++) {
                const int row = rb + mf * 16;
                a[mf][0] = uX[(row + g    ) * 132 + k0 + t4    ];
                a[mf][1] = uX[(row + g + 8) * 132 + k0 + t4    ];
                a[mf][2] = uX[(row + g    ) * 132 + k0 + t4 + 4];
                a[mf][3] = uX[(row + g + 8) * 132 + k0 + t4 + 4];
            }
            uint32_t b[8][2];
#pragma unroll
            for (int nf = 0; nf < 8; nf++) {
                b[nf][0] = uB[(nf * 8 + g) * 132 + k0 + t4    ];
                b[nf][1] = uB[(nf * 8 + g) * 132 + k0 + t4 + 4];
            }
#pragma unroll
            for (int mf = 0; mf < 2; mf++)
#pragma unroll
                for (int nf = 0; nf < 8; nf++)
                    MMA_TF32_16x8x8(acc[mf][nf], a[mf], b[nf]);
        }

        // ---- store D: warp tile 32 x 64 -> g_y
#pragma unroll
        for (int mf = 0; mf < 2; mf++) {
            const int r0 = n0 + rb + mf * 16 + g;
            const int r1 = r0 + 8;
#pragma unroll
            for (int nf = 0; nf < 8; nf++) {
                const int col = tile * 64 + nf * 8 + t4 * 2;
                if (r0 < N_PTS)
                    *(float2*)(g_y + (size_t)r0 * NCHP + col) =
                        make_float2(acc[mf][nf][0], acc[mf][nf][1]);
                if (r1 < N_PTS)
                    *(float2*)(g_y + (size_t)r1 * NCHP + col) =
                        make_float2(acc[mf][nf][2], acc[mf][nf][3]);
            }
        }
    }
}

// ---------------------------------------------------------------------------
// Kernel 2: warp-per-point. q_pre[v] = sum_k m * y[idx,k,v]; qf = relu(bn);
//           choice = sum_c relu(qf . A[:,c] + b_c)   -> g_choice
// ---------------------------------------------------------------------------
__global__ __launch_bounds__(256) void k_qchoice(
    const float* __restrict__ q_gamma, const float* __restrict__ q_beta,
    const float* __restrict__ b_choice,
    const int* __restrict__ nbr_idx, const int* __restrict__ nbr_mask)
{
    __shared__ float sA[VEC * PLANES];
    const int tid = threadIdx.x, lane = tid & 31, w = tid >> 5;
    for (int i = tid; i < VEC * PLANES / 4; i += 256)
        ((float4*)sA)[i] = __ldg((const float4*)g_A + i);
    __syncthreads();

    const int n = blockIdx.x * 8 + w;   // grid = 12500 -> exactly N_PTS warps

    int idxv = 0, mk = 0;
    if (lane < KOFF) {
        idxv = __ldg(nbr_idx  + lane * N_PTS + n);
        mk   = __ldg(nbr_mask + lane * N_PTS + n);
    }
    float acc = 0.f;
#pragma unroll
    for (int k = 0; k < KOFF; k++) {
        const int id = __shfl_sync(0xffffffffu, idxv, k);
        const int m  = __shfl_sync(0xffffffffu, mk,   k);
        float t = 0.f;
        if (m && lane < VEC) t = __ldg(g_y + (size_t)id * NCHP + k * VEC + lane);
        acc += t;
    }
    float qf = 0.f;
    if (lane < VEC) {
        qf = fmaf(acc, __ldg(q_gamma + lane), __ldg(q_beta + lane));
        qf = fmaxf(qf, 0.f);
    }
    float s0 = __ldg(b_choice + lane);
    float s1 = __ldg(b_choice + 32 + lane);
    float s2 = __ldg(b_choice + 64 + lane);
    float s3 = __ldg(b_choice + 96 + lane);
#pragma unroll
    for (int v = 0; v < VEC; v++) {
        const float qv = __shfl_sync(0xffffffffu, qf, v);
        s0 = fmaf(qv, sA[v * PLANES +      lane], s0);
        s1 = fmaf(qv, sA[v * PLANES + 32 + lane], s1);
        s2 = fmaf(qv, sA[v * PLANES + 64 + lane], s2);
        s3 = fmaf(qv, sA[v * PLANES + 96 + lane], s3);
    }
    float tsum = fmaxf(s0, 0.f) + fmaxf(s1, 0.f) + fmaxf(s2, 0.f) + fmaxf(s3, 0.f);
#pragma unroll
    for (int off = 16; off > 0; off >>= 1)
        tsum += __shfl_xor_sync(0xffffffffu, tsum, off);
    if (lane == 0) g_choice[n] = tsum;
}

// ---------------------------------------------------------------------------
// Kernel 3: v_f = relu((x@W_v)*gamma+beta) + repeat(coords@W_pos + b_pos, 8)
// Persistent blocks, tile = 32 points, thread tile 4p x 8c, fp32.
// ---------------------------------------------------------------------------
__global__ __launch_bounds__(128) void k_vf(
    const float* __restrict__ x, const float* __restrict__ coords,
    const float* __restrict__ W_v, const float* __restrict__ v_gamma,
    const float* __restrict__ v_beta, const float* __restrict__ W_pos,
    const float* __restrict__ b_pos)
{
    extern __shared__ float sm[];
    float* sW = sm;                  // 128 * 132
    float* sX = sm + PLANES * 132;   // 32 * 132
    float* sC = sX + 32 * 132;       // 32 * 4

    const int tid = threadIdx.x;
    const int pg = tid >> 4, cg = tid & 15;

    for (int r = 0; r < 32; r++) {
        const int id = r * 128 + tid;
        const int j = id >> 5, c0 = (id & 31) * 4;
        const float4 v = __ldg((const float4*)W_v + id);
        sW[(((c0+0)&7)*16 + ((c0+0)>>3))*132 + j] = v.x;
        sW[(((c0+1)&7)*16 + ((c0+1)>>3))*132 + j] = v.y;
        sW[(((c0+2)&7)*16 + ((c0+2)>>3))*132 + j] = v.z;
        sW[(((c0+3)&7)*16 + ((c0+3)>>3))*132 + j] = v.w;
    }
    float gam[8], bet[8];
#pragma unroll
    for (int t = 0; t < 8; t++) {
        const int c = cg * 8 + t;
        gam[t] = __ldg(v_gamma + c); bet[t] = __ldg(v_beta + c);
    }
    const float wp0 = __ldg(W_pos + 0 * VEC + cg);
    const float wp1 = __ldg(W_pos + 1 * VEC + cg);
    const float wp2 = __ldg(W_pos + 2 * VEC + cg);
    const float bp  = __ldg(b_pos + cg);

    for (int tile = blockIdx.x; tile < N_TILES; tile += gridDim.x) {
        __syncthreads();
        for (int r = 0; r < 8; r++) {
            const int id = r * 128 + tid;
            const int p = id >> 5, c4 = id & 31;
            const int n = tile * 32 + p;
            *(float4*)&sX[p * 132 + c4 * 4] =
                __ldg((const float4*)(x + (size_t)n * PLANES) + c4);
        }
        if (tid < 32) {
            const int n = tile * 32 + tid;
            sC[tid*4+0] = __ldg(coords + n*3 + 0);
            sC[tid*4+1] = __ldg(coords + n*3 + 1);
            sC[tid*4+2] = __ldg(coords + n*3 + 2);
        }
        __syncthreads();

        float acc[4][8];
#pragma unroll
        for (int i = 0; i < 4; i++)
#pragma unroll
            for (int t = 0; t < 8; t++) acc[i][t] = 0.f;

        const float* xb = &sX[(pg * 4) * 132];
        const float* wb = &sW[cg * 132];
#pragma unroll 2
        for (int jj = 0; jj < 32; jj++) {
            float4 xv[4];
#pragma unroll
            for (int i = 0; i < 4; i++) xv[i] = *(const float4*)&xb[i * 132 + jj * 4];
#pragma unroll
            for (int t = 0; t < 8; t++) {
                const float4 wv = *(const float4*)&wb[t * 16 * 132 + jj * 4];
#pragma unroll
                for (int i = 0; i < 4; i++) {
                    acc[i][t] = fmaf(xv[i].x, wv.x, acc[i][t]);
                    acc[i][t] = fmaf(xv[i].y, wv.y, acc[i][t]);
                    acc[i][t] = fmaf(xv[i].z, wv.z, acc[i][t]);
                    acc[i][t] = fmaf(xv[i].w, wv.w, acc[i][t]);
                }
            }
        }
#pragma unroll
        for (int i = 0; i < 4; i++) {
            const int p = pg * 4 + i;
            const int n = tile * 32 + p;
            const float pos = fmaf(sC[p*4+0], wp0,
                              fmaf(sC[p*4+1], wp1,
                              fmaf(sC[p*4+2], wp2, bp)));
            float o[8];
#pragma unroll
            for (int t = 0; t < 8; t++) {
                const float r = fmaf(acc[i][t], gam[t], bet[t]);
                o[t] = fmaxf(r, 0.f) + pos;
            }
            float4* dst = (float4*)(g_vf + (size_t)n * PLANES + cg * 8);
            dst[0] = make_float4(o[0], o[1], o[2], o[3]);
            dst[1] = make_float4(o[4], o[5], o[6], o[7]);
        }
    }
}

// ---------------------------------------------------------------------------
// Kernel 4: warp-per-point softmax + v_f gather-aggregate into smem, then
//           fp32 tile GEMM out = relu((agg@W_out)*gamma+beta) + x.
// ---------------------------------------------------------------------------
__global__ __launch_bounds__(128) void k_attn_out(
    const float* __restrict__ x, const float* __restrict__ W_out,
    const float* __restrict__ out_gamma, const float* __restrict__ out_beta,
    const int* __restrict__ nbr_idx, const int* __restrict__ nbr_mask,
    float* __restrict__ out)
{
    extern __shared__ float sm[];
    float* sW   = sm;                 // 128 * 132
    float* sAgg = sm + PLANES * 132;  // 32 * 132

    const int tid = threadIdx.x;
    const int lane = tid & 31, w = tid >> 5;
    const int pg = tid >> 4, cg = tid & 15;

    for (int r = 0; r < 32; r++) {
        const int id = r * 128 + tid;
        const int j = id >> 5, c0 = (id & 31) * 4;
        const float4 v = __ldg((const float4*)W_out + id);
        sW[(((c0+0)&7)*16 + ((c0+0)>>3))*132 + j] = v.x;
        sW[(((c0+1)&7)*16 + ((c0+1)>>3))*132 + j] = v.y;
        sW[(((c0+2)&7)*16 + ((c0+2)>>3))*132 + j] = v.z;
        sW[(((c0+3)&7)*16 + ((c0+3)>>3))*132 + j] = v.w;
    }
    float gam[8], bet[8];
#pragma unroll
    for (int t = 0; t < 8; t++) {
        const int c = cg * 8 + t;
        gam[t] = __ldg(out_gamma + c); bet[t] = __ldg(out_beta + c);
    }
    const float csum = g_csum;

    for (int tile = blockIdx.x; tile < N_TILES; tile += gridDim.x) {
        __syncthreads();
        // ---- phase A: each warp aggregates 8 points
#pragma unroll 1
        for (int pp = 0; pp < 8; pp++) {
            const int pl = w * 8 + pp;
            const int n  = tile * 32 + pl;
            const float chn = __ldg(g_choice + n);
            int idxv = 0, mk = 0;
            if (lane < KOFF) {
                idxv = __ldg(nbr_idx  + lane * N_PTS + n);
                mk   = __ldg(nbr_mask + lane * N_PTS + n);
            }
            float s = (mk != 0) ? chn * __ldg(g_choice + idxv) * csum : -3.0e38f;
            float mx = s;
#pragma unroll
            for (int off = 16; off > 0; off >>= 1)
                mx = fmaxf(mx, __shfl_xor_sync(0xffffffffu, mx, off));
            const float e = (mk != 0) ? __expf(s - mx) : 0.f;
            float den = e;
#pragma unroll
            for (int off = 16; off > 0; off >>= 1)
                den += __shfl_xor_sync(0xffffffffu, den, off);
            const float rd = 1.0f / den;

            float ax = 0.f, ay = 0.f, az = 0.f, aw2 = 0.f;
#pragma unroll
            for (int k0 = 0; k0 < KOFF; k0 += 9) {
                float wk[9]; int ik[9];
#pragma unroll
                for (int q = 0; q < 9; q++) {
                    wk[q] = __shfl_sync(0xffffffffu, e,    k0 + q);
                    ik[q] = __shfl_sync(0xffffffffu, idxv, k0 + q);
                }
                float4 t[9];
#pragma unroll
                for (int q = 0; q < 9; q++) {
                    t[q] = make_float4(0.f, 0.f, 0.f, 0.f);
                    if (wk[q] != 0.f)
                        t[q] = __ldg((const float4*)(g_vf + (size_t)ik[q] * PLANES) + lane);
                }
#pragma unroll
                for (int q = 0; q < 9; q++) {
                    ax  = fmaf(wk[q], t[q].x, ax);
                    ay  = fmaf(wk[q], t[q].y, ay);
                    az  = fmaf(wk[q], t[q].z, az);
                    aw2 = fmaf(wk[q], t[q].w, aw2);
                }
            }
            *(float4*)&sAgg[pl * 132 + lane * 4] =
                make_float4(ax * rd, ay * rd, az * rd, aw2 * rd);
        }
        __syncthreads();

        // ---- phase B: 32x128 @ 128x128 tile GEMM + epilogue
        float acc[4][8];
#pragma unroll
        for (int i = 0; i < 4; i++)
#pragma unroll
            for (int t = 0; t < 8; t++) acc[i][t] = 0.f;

        const float* xb = &sAgg[(pg * 4) * 132];
        const float* wb = &sW[cg * 132];
#pragma unroll 2
        for (int jj = 0; jj < 32; jj++) {
            float4 xv[4];
#pragma unroll
            for (int i = 0; i < 4; i++) xv[i] = *(const float4*)&xb[i * 132 + jj * 4];
#pragma unroll
            for (int t = 0; t < 8; t++) {
                const float4 wv = *(const float4*)&wb[t * 16 * 132 + jj * 4];
#pragma unroll
                for (int i = 0; i < 4; i++) {
                    acc[i][t] = fmaf(xv[i].x, wv.x, acc[i][t]);
                    acc[i][t] = fmaf(xv[i].y, wv.y, acc[i][t]);
                    acc[i][t] = fmaf(xv[i].z, wv.z, acc[i][t]);
                    acc[i][t] = fmaf(xv[i].w, wv.w, acc[i][t]);
                }
            }
        }
#pragma unroll
        for (int i = 0; i < 4; i++) {
            const int n = tile * 32 + pg * 4 + i;
            const float4* xr = (const float4*)(x + (size_t)n * PLANES + cg * 8);
            const float4 x0 = __ldg(xr), x1 = __ldg(xr + 1);
            float o[8];
#pragma unroll
            for (int t = 0; t < 8; t++) {
                const float r = fmaf(acc[i][t], gam[t], bet[t]);
                o[t] = fmaxf(r, 0.f);
            }
            float4* dst = (float4*)(out + (size_t)n * PLANES + cg * 8);
            dst[0] = make_float4(o[0] + x0.x, o[1] + x0.y, o[2] + x0.z, o[3] + x0.w);
            dst[1] = make_float4(o[4] + x1.x, o[5] + x1.y, o[6] + x1.z, o[7] + x1.w);
        }
    }
}

// ---------------------------------------------------------------------------
extern "C" void kernel_launch(void* const* d_in, const int* in_sizes, int n_in,
                              void* d_out, int out_size)
{
    const float* x         = (const float*)d_in[0];
    const float* coords    = (const float*)d_in[1];
    const float* W_q       = (const float*)d_in[2];
    const float* q_gamma   = (const float*)d_in[3];
    const float* q_beta    = (const float*)d_in[4];
    const float* W_v       = (const float*)d_in[5];
    const float* v_gamma   = (const float*)d_in[6];
    const float* v_beta    = (const float*)d_in[7];
    const float* codebook  = (const float*)d_in[8];
    const float* W_choice  = (const float*)d_in[9];
    const float* b_choice  = (const float*)d_in[10];
    const float* W_pos     = (const float*)d_in[11];
    const float* b_pos     = (const float*)d_in[12];
    const float* W_out     = (const float*)d_in[13];
    const float* out_gamma = (const float*)d_in[14];
    const float* out_beta  = (const float*)d_in[15];
    const int*   nbr_idx   = (const int*)d_in[16];
    const int*   nbr_mask  = (const int*)d_in[17];
    float* out = (float*)d_out;

    const int smem_vf   = (PLANES * 132 + 32 * 132 + 128) * (int)sizeof(float);
    const int smem_attn = (PLANES * 132 + 32 * 132) * (int)sizeof(float);
    cudaFuncSetAttribute(k_ygemm_mma, cudaFuncAttributeMaxDynamicSharedMemorySize, YG_SMEM);
    cudaFuncSetAttribute(k_vf,        cudaFuncAttributeMaxDynamicSharedMemorySize, smem_vf);
    cudaFuncSetAttribute(k_attn_out,  cudaFuncAttributeMaxDynamicSharedMemorySize, smem_attn);

    k_prep<<<1, 128>>>(codebook, W_choice);
    k_prepW<<<NCHP, 128>>>(W_q);
    k_ygemm_mma<<<(N_PTS + 127) / 128, 128, YG_SMEM>>>(x);
    k_vf<<<296, 128, smem_vf>>>(x, coords, W_v, v_gamma, v_beta, W_pos, b_pos);
    k_qchoice<<<N_PTS / 8, 256>>>(q_gamma, q_beta, b_choice, nbr_idx, nbr_mask);
    k_attn_out<<<296, 128, smem_attn>>>(x, W_out, out_gamma, out_beta,
                                        nbr_idx, nbr_mask, out);
}

// round 11
// speedup vs baseline: 2.4190x; 1.1102x over previous
#include <cuda_runtime.h>
#include <math.h>
#include <stdint.h>

#define N_PTS  100000
#define PLANES 128
#define VEC    16
#define KOFF   27
#define NCH    432
#define NCHP   448        // padded 28*16 -> 1792B rows (128B aligned)
#define NCOLS  704        // 448 (W_q) + 128 (W_v) + 128 (W_out)

__device__ __forceinline__ float to_tf32(float f) {
    float r;
    asm("cvt.rna.tf32.f32 %0, %1;" : "=f"(r) : "f"(f));
    return r;
}

#define MMA_TF32_16x8x8(d, a, b) \
    asm volatile( \
        "mma.sync.aligned.m16n8k8.row.col.f32.tf32.tf32.f32 " \
        "{%0,%1,%2,%3}, {%4,%5,%6,%7}, {%8,%9}, {%0,%1,%2,%3};" \
        : "+f"((d)[0]), "+f"((d)[1]), "+f"((d)[2]), "+f"((d)[3]) \
        : "r"((a)[0]), "r"((a)[1]), "r"((a)[2]), "r"((a)[3]), \
          "r"((b)[0]), "r"((b)[1]))

// Scratch (__device__ globals: allocation-free rule)
__device__ float g_y[(size_t)N_PTS * NCHP];       // 179.2 MB
__device__ float g_choice[N_PTS];
__device__ float g_vf[(size_t)N_PTS * PLANES];    // 51.2 MB
__device__ float g_A[VEC * PLANES];
__device__ float g_csum;
__device__ float g_Wt[NCOLS * PLANES];            // all weights, transposed, tf32

// ---------------------------------------------------------------------------
// Kernel 0a: fold codebook into W_choice:  A[v][c], and csum = ||codebook||^2
// ---------------------------------------------------------------------------
__global__ void k_prep(const float* __restrict__ codebook,
                       const float* __restrict__ W_choice)
{
    const int c = threadIdx.x;   // 128 threads
    for (int v = 0; v < VEC; v++) {
        float s = 0.f;
#pragma unroll
        for (int j = 0; j < 8; j++) {
            const int jj = v * 8 + j;
            s = fmaf(__ldg(codebook + jj), __ldg(W_choice + jj * PLANES + c), s);
        }
        g_A[v * PLANES + c] = s;
    }
    if (c == 0) {
        float cs = 0.f;
        for (int j = 0; j < PLANES; j++) { float t = __ldg(codebook + j); cs = fmaf(t, t, cs); }
        g_csum = cs;
    }
}

// ---------------------------------------------------------------------------
// Kernel 0b: combined weight transpose -> g_Wt[col][j], tf32-rounded.
//   col 0..447  : W_q  (col = k*16+v, zero for k>=27)
//   col 448..575: W_v  (out channel col-448)
//   col 576..703: W_out(out channel col-576)
// ---------------------------------------------------------------------------
__global__ void k_prepW(const float* __restrict__ W_q,
                        const float* __restrict__ W_v,
                        const float* __restrict__ W_out)
{
    const int col = blockIdx.x;   // 0..703
    const int j   = threadIdx.x;  // 0..127
    float v = 0.f;
    if (col < NCHP) {
        if (col < NCH) {
            const int k = col >> 4, vv = col & 15;
            v = __ldg(W_q + (size_t)k * PLANES * VEC + j * VEC + vv);
        }
    } else if (col < NCHP + PLANES) {
        v = __ldg(W_v + j * PLANES + (col - NCHP));
    } else {
        v = __ldg(W_out + j * PLANES + (col - NCHP - PLANES));
    }
    g_Wt[col * PLANES + j] = to_tf32(v);
}

// ---------------------------------------------------------------------------
// Kernel 1: fused tf32 mma GEMM over 9 N-tiles of 64:
//   tiles 0..6 : y[n, col]  = x[n,:] . W_q-col     -> g_y
//   tiles 7..8 : v_f[n, c]  = relu((x@W_v)*g+b)+pos -> g_vf
// Block = 128 thr (4 warps), M-tile 128 points, K=128.
// ---------------------------------------------------------------------------
#define G1_SMEM ((PLANES * 132 + 64 * 132 + PLANES * 17) * 4)

__global__ __launch_bounds__(128) void k_gemm1(
    const float* __restrict__ x, const float* __restrict__ coords,
    const float* __restrict__ W_pos, const float* __restrict__ b_pos,
    const float* __restrict__ v_gamma, const float* __restrict__ v_beta)
{
    extern __shared__ float sm[];
    float* sX   = sm;                             // 128 * 132
    float* sB   = sm + PLANES * 132;              // 64 * 132
    float* sPos = sm + PLANES * 132 + 64 * 132;   // 128 * 17

    const int tid  = threadIdx.x;
    const int wid  = tid >> 5, lane = tid & 31;
    const int g    = lane >> 2, t4 = lane & 3;
    const int n0   = blockIdx.x * 128;

    // ---- stage A tile (tf32-rounded), coalesced float4 reads
    for (int it = 0; it < 32; it++) {
        const int id = it * 128 + tid;
        const int p = id >> 5, c4 = id & 31;
        const int n = n0 + p;
        float4 v = make_float4(0.f, 0.f, 0.f, 0.f);
        if (n < N_PTS) v = __ldg((const float4*)(x + (size_t)n * PLANES) + c4);
        v.x = to_tf32(v.x); v.y = to_tf32(v.y); v.z = to_tf32(v.z); v.w = to_tf32(v.w);
        *(float4*)&sX[p * 132 + c4 * 4] = v;
    }
    // ---- positional encodings: sPos[row][grp]
    {
        const int n = n0 + tid;
        float c0 = 0.f, c1 = 0.f, c2 = 0.f;
        if (n < N_PTS) {
            c0 = __ldg(coords + n * 3 + 0);
            c1 = __ldg(coords + n * 3 + 1);
            c2 = __ldg(coords + n * 3 + 2);
        }
#pragma unroll
        for (int gr = 0; gr < VEC; gr++) {
            sPos[tid * 17 + gr] =
                fmaf(c0, __ldg(W_pos + gr),
                fmaf(c1, __ldg(W_pos + VEC + gr),
                fmaf(c2, __ldg(W_pos + 2 * VEC + gr), __ldg(b_pos + gr))));
        }
    }

    const uint32_t* uX = (const uint32_t*)sX;
    const uint32_t* uB = (const uint32_t*)sB;
    const int rb = wid * 32;   // warp's row base within tile

    for (int tile = 0; tile < 9; tile++) {
        __syncthreads();
        // ---- stage B tile: 64 cols x 128 k (tf32 in g_Wt)
        for (int it = 0; it < 16; it++) {
            const int id = it * 128 + tid;
            const int r = id >> 5, c4 = id & 31;
            *(float4*)&sB[r * 132 + c4 * 4] =
                __ldg((const float4*)(g_Wt + (size_t)(tile * 64 + r) * PLANES) + c4);
        }
        __syncthreads();

        float acc[2][8][4];
#pragma unroll
        for (int mf = 0; mf < 2; mf++)
#pragma unroll
            for (int nf = 0; nf < 8; nf++)
#pragma unroll
                for (int q = 0; q < 4; q++) acc[mf][nf][q] = 0.f;

#pragma unroll 2
        for (int kb = 0; kb < 16; kb++) {
            const int k0 = kb * 8;
            uint32_t a[2][4];
#pragma unroll
            for (int mf = 0; mf < 2; mf++) {
                const int row = rb + mf * 16;
                a[mf][0] = uX[(row + g    ) * 132 + k0 + t4    ];
                a[mf][1] = uX[(row + g + 8) * 132 + k0 + t4    ];
                a[mf][2] = uX[(row + g    ) * 132 + k0 + t4 + 4];
                a[mf][3] = uX[(row + g + 8) * 132 + k0 + t4 + 4];
            }
            uint32_t b[8][2];
#pragma unroll
            for (int nf = 0; nf < 8; nf++) {
                b[nf][0] = uB[(nf * 8 + g) * 132 + k0 + t4    ];
                b[nf][1] = uB[(nf * 8 + g) * 132 + k0 + t4 + 4];
            }
#pragma unroll
            for (int mf = 0; mf < 2; mf++)
#pragma unroll
                for (int nf = 0; nf < 8; nf++)
                    MMA_TF32_16x8x8(acc[mf][nf], a[mf], b[nf]);
        }

        if (tile < 7) {
            // ---- store y: warp tile 32 x 64 -> g_y
#pragma unroll
            for (int mf = 0; mf < 2; mf++) {
                const int r0 = n0 + rb + mf * 16 + g;
                const int r1 = r0 + 8;
#pragma unroll
                for (int nf = 0; nf < 8; nf++) {
                    const int col = tile * 64 + nf * 8 + t4 * 2;
                    if (r0 < N_PTS)
                        *(float2*)(g_y + (size_t)r0 * NCHP + col) =
                            make_float2(acc[mf][nf][0], acc[mf][nf][1]);
                    if (r1 < N_PTS)
                        *(float2*)(g_y + (size_t)r1 * NCHP + col) =
                            make_float2(acc[mf][nf][2], acc[mf][nf][3]);
                }
            }
        } else {
            // ---- v_f epilogue: BN + ReLU + pos -> g_vf
            const int cb = (tile - 7) * 64;
#pragma unroll
            for (int mf = 0; mf < 2; mf++) {
                const int rl0 = rb + mf * 16 + g;     // local rows
                const int rl1 = rl0 + 8;
                const int r0 = n0 + rl0, r1 = n0 + rl1;
#pragma unroll
                for (int nf = 0; nf < 8; nf++) {
                    const int col = cb + nf * 8 + t4 * 2;
                    const float gm0 = __ldg(v_gamma + col),     bt0 = __ldg(v_beta + col);
                    const float gm1 = __ldg(v_gamma + col + 1), bt1 = __ldg(v_beta + col + 1);
                    const int grp = col >> 3;
                    if (r0 < N_PTS) {
                        const float pos = sPos[rl0 * 17 + grp];
                        const float o0 = fmaxf(fmaf(acc[mf][nf][0], gm0, bt0), 0.f) + pos;
                        const float o1 = fmaxf(fmaf(acc[mf][nf][1], gm1, bt1), 0.f) + pos;
                        *(float2*)(g_vf + (size_t)r0 * PLANES + col) = make_float2(o0, o1);
                    }
                    if (r1 < N_PTS) {
                        const float pos = sPos[rl1 * 17 + grp];
                        const float o0 = fmaxf(fmaf(acc[mf][nf][2], gm0, bt0), 0.f) + pos;
                        const float o1 = fmaxf(fmaf(acc[mf][nf][3], gm1, bt1), 0.f) + pos;
                        *(float2*)(g_vf + (size_t)r1 * PLANES + col) = make_float2(o0, o1);
                    }
                }
            }
        }
    }
}

// ---------------------------------------------------------------------------
// Kernel 2: warp-per-point. q_pre[v] = sum_k m * y[idx,k,v]; qf = relu(bn);
//           choice = sum_c relu(qf . A[:,c] + b_c)   -> g_choice
// ---------------------------------------------------------------------------
__global__ __launch_bounds__(256) void k_qchoice(
    const float* __restrict__ q_gamma, const float* __restrict__ q_beta,
    const float* __restrict__ b_choice,
    const int* __restrict__ nbr_idx, const int* __restrict__ nbr_mask)
{
    __shared__ float sA[VEC * PLANES];
    const int tid = threadIdx.x, lane = tid & 31, w = tid >> 5;
    for (int i = tid; i < VEC * PLANES / 4; i += 256)
        ((float4*)sA)[i] = __ldg((const float4*)g_A + i);
    __syncthreads();

    const int n = blockIdx.x * 8 + w;   // grid = 12500 -> exactly N_PTS warps

    int idxv = 0, mk = 0;
    if (lane < KOFF) {
        idxv = __ldg(nbr_idx  + lane * N_PTS + n);
        mk   = __ldg(nbr_mask + lane * N_PTS + n);
    }
    float acc = 0.f;
#pragma unroll
    for (int k = 0; k < KOFF; k++) {
        const int id = __shfl_sync(0xffffffffu, idxv, k);
        const int m  = __shfl_sync(0xffffffffu, mk,   k);
        float t = 0.f;
        if (m && lane < VEC) t = __ldg(g_y + (size_t)id * NCHP + k * VEC + lane);
        acc += t;
    }
    float qf = 0.f;
    if (lane < VEC) {
        qf = fmaf(acc, __ldg(q_gamma + lane), __ldg(q_beta + lane));
        qf = fmaxf(qf, 0.f);
    }
    float s0 = __ldg(b_choice + lane);
    float s1 = __ldg(b_choice + 32 + lane);
    float s2 = __ldg(b_choice + 64 + lane);
    float s3 = __ldg(b_choice + 96 + lane);
#pragma unroll
    for (int v = 0; v < VEC; v++) {
        const float qv = __shfl_sync(0xffffffffu, qf, v);
        s0 = fmaf(qv, sA[v * PLANES +      lane], s0);
        s1 = fmaf(qv, sA[v * PLANES + 32 + lane], s1);
        s2 = fmaf(qv, sA[v * PLANES + 64 + lane], s2);
        s3 = fmaf(qv, sA[v * PLANES + 96 + lane], s3);
    }
    float tsum = fmaxf(s0, 0.f) + fmaxf(s1, 0.f) + fmaxf(s2, 0.f) + fmaxf(s3, 0.f);
#pragma unroll
    for (int off = 16; off > 0; off >>= 1)
        tsum += __shfl_xor_sync(0xffffffffu, tsum, off);
    if (lane == 0) g_choice[n] = tsum;
}

// ---------------------------------------------------------------------------
// Kernel 3: per 128-pt tile: warp softmax + v_f gather-aggregate into sAgg
//           (tf32), then tf32 mma GEMM out = relu((agg@W_out)*g+b) + x.
// ---------------------------------------------------------------------------
#define AT_SMEM ((PLANES * 132 + 64 * 132) * 4)

__global__ __launch_bounds__(128) void k_attn_out(
    const float* __restrict__ x,
    const float* __restrict__ out_gamma, const float* __restrict__ out_beta,
    const int* __restrict__ nbr_idx, const int* __restrict__ nbr_mask,
    float* __restrict__ out)
{
    extern __shared__ float sm[];
    float* sAgg = sm;                 // 128 * 132
    float* sB   = sm + PLANES * 132;  // 64 * 132

    const int tid = threadIdx.x;
    const int wid = tid >> 5, lane = tid & 31;
    const int g   = lane >> 2, t4 = lane & 3;
    const int n0  = blockIdx.x * 128;
    const float csum = g_csum;

    // ---- phase A: each warp aggregates 32 points
#pragma unroll 1
    for (int pp = 0; pp < 32; pp++) {
        const int pl = wid * 32 + pp;
        const int n  = n0 + pl;
        if (n >= N_PTS) {
            *(float4*)&sAgg[pl * 132 + lane * 4] = make_float4(0.f, 0.f, 0.f, 0.f);
            continue;
        }
        const float chn = __ldg(g_choice + n);
        int idxv = 0, mk = 0;
        if (lane < KOFF) {
            idxv = __ldg(nbr_idx  + lane * N_PTS + n);
            mk   = __ldg(nbr_mask + lane * N_PTS + n);
        }
        float s = (mk != 0) ? chn * __ldg(g_choice + idxv) * csum : -3.0e38f;
        float mx = s;
#pragma unroll
        for (int off = 16; off > 0; off >>= 1)
            mx = fmaxf(mx, __shfl_xor_sync(0xffffffffu, mx, off));
        const float e = (mk != 0) ? __expf(s - mx) : 0.f;
        float den = e;
#pragma unroll
        for (int off = 16; off > 0; off >>= 1)
            den += __shfl_xor_sync(0xffffffffu, den, off);
        const float rd = 1.0f / den;

        float ax = 0.f, ay = 0.f, az = 0.f, aw2 = 0.f;
#pragma unroll
        for (int k0 = 0; k0 < KOFF; k0 += 9) {
            float wk[9]; int ik[9];
#pragma unroll
            for (int q = 0; q < 9; q++) {
                wk[q] = __shfl_sync(0xffffffffu, e,    k0 + q);
                ik[q] = __shfl_sync(0xffffffffu, idxv, k0 + q);
            }
            float4 t[9];
#pragma unroll
            for (int q = 0; q < 9; q++) {
                t[q] = make_float4(0.f, 0.f, 0.f, 0.f);
                if (wk[q] != 0.f)
                    t[q] = __ldg((const float4*)(g_vf + (size_t)ik[q] * PLANES) + lane);
            }
#pragma unroll
            for (int q = 0; q < 9; q++) {
                ax  = fmaf(wk[q], t[q].x, ax);
                ay  = fmaf(wk[q], t[q].y, ay);
                az  = fmaf(wk[q], t[q].z, az);
                aw2 = fmaf(wk[q], t[q].w, aw2);
            }
        }
        *(float4*)&sAgg[pl * 132 + lane * 4] =
            make_float4(to_tf32(ax * rd), to_tf32(ay * rd),
                        to_tf32(az * rd), to_tf32(aw2 * rd));
    }

    // ---- phase B: 128x128 @ 128x128 tf32 mma GEMM (2 N-tiles of 64)
    const uint32_t* uX = (const uint32_t*)sAgg;
    const uint32_t* uB = (const uint32_t*)sB;
    const int rb = wid * 32;

    for (int tile = 0; tile < 2; tile++) {
        __syncthreads();
        for (int it = 0; it < 16; it++) {
            const int id = it * 128 + tid;
            const int r = id >> 5, c4 = id & 31;
            *(float4*)&sB[r * 132 + c4 * 4] =
                __ldg((const float4*)(g_Wt + (size_t)(NCHP + PLANES + tile * 64 + r) * PLANES) + c4);
        }
        __syncthreads();

        float acc[2][8][4];
#pragma unroll
        for (int mf = 0; mf < 2; mf++)
#pragma unroll
            for (int nf = 0; nf < 8; nf++)
#pragma unroll
                for (int q = 0; q < 4; q++) acc[mf][nf][q] = 0.f;

#pragma unroll 2
        for (int kb = 0; kb < 16; kb++) {
            const int k0 = kb * 8;
            uint32_t a[2][4];
#pragma unroll
            for (int mf = 0; mf < 2; mf++) {
                const int row = rb + mf * 16;
                a[mf][0] = uX[(row + g    ) * 132 + k0 + t4    ];
                a[mf][1] = uX[(row + g + 8) * 132 + k0 + t4    ];
                a[mf][2] = uX[(row + g    ) * 132 + k0 + t4 + 4];
                a[mf][3] = uX[(row + g + 8) * 132 + k0 + t4 + 4];
            }
            uint32_t b[8][2];
#pragma unroll
            for (int nf = 0; nf < 8; nf++) {
                b[nf][0] = uB[(nf * 8 + g) * 132 + k0 + t4    ];
                b[nf][1] = uB[(nf * 8 + g) * 132 + k0 + t4 + 4];
            }
#pragma unroll
            for (int mf = 0; mf < 2; mf++)
#pragma unroll
                for (int nf = 0; nf < 8; nf++)
                    MMA_TF32_16x8x8(acc[mf][nf], a[mf], b[nf]);
        }

        // ---- epilogue: BN + ReLU + residual
#pragma unroll
        for (int mf = 0; mf < 2; mf++) {
            const int r0 = n0 + rb + mf * 16 + g;
            const int r1 = r0 + 8;
#pragma unroll
            for (int nf = 0; nf < 8; nf++) {
                const int col = tile * 64 + nf * 8 + t4 * 2;
                const float gm0 = __ldg(out_gamma + col),     bt0 = __ldg(out_beta + col);
                const float gm1 = __ldg(out_gamma + col + 1), bt1 = __ldg(out_beta + col + 1);
                if (r0 < N_PTS) {
                    const float2 xv = __ldg((const float2*)(x + (size_t)r0 * PLANES + col));
                    const float o0 = fmaxf(fmaf(acc[mf][nf][0], gm0, bt0), 0.f) + xv.x;
                    const float o1 = fmaxf(fmaf(acc[mf][nf][1], gm1, bt1), 0.f) + xv.y;
                    *(float2*)(out + (size_t)r0 * PLANES + col) = make_float2(o0, o1);
                }
                if (r1 < N_PTS) {
                    const float2 xv = __ldg((const float2*)(x + (size_t)r1 * PLANES + col));
                    const float o0 = fmaxf(fmaf(acc[mf][nf][2], gm0, bt0), 0.f) + xv.x;
                    const float o1 = fmaxf(fmaf(acc[mf][nf][3], gm1, bt1), 0.f) + xv.y;
                    *(float2*)(out + (size_t)r1 * PLANES + col) = make_float2(o0, o1);
                }
            }
        }
    }
}

// ---------------------------------------------------------------------------
extern "C" void kernel_launch(void* const* d_in, const int* in_sizes, int n_in,
                              void* d_out, int out_size)
{
    const float* x         = (const float*)d_in[0];
    const float* coords    = (const float*)d_in[1];
    const float* W_q       = (const float*)d_in[2];
    const float* q_gamma   = (const float*)d_in[3];
    const float* q_beta    = (const float*)d_in[4];
    const float* W_v       = (const float*)d_in[5];
    const float* v_gamma   = (const float*)d_in[6];
    const float* v_beta    = (const float*)d_in[7];
    const float* codebook  = (const float*)d_in[8];
    const float* W_choice  = (const float*)d_in[9];
    const float* b_choice  = (const float*)d_in[10];
    const float* W_pos     = (const float*)d_in[11];
    const float* b_pos     = (const float*)d_in[12];
    const float* W_out     = (const float*)d_in[13];
    const float* out_gamma = (const float*)d_in[14];
    const float* out_beta  = (const float*)d_in[15];
    const int*   nbr_idx   = (const int*)d_in[16];
    const int*   nbr_mask  = (const int*)d_in[17];
    float* out = (float*)d_out;

    cudaFuncSetAttribute(k_gemm1,    cudaFuncAttributeMaxDynamicSharedMemorySize, G1_SMEM);
    cudaFuncSetAttribute(k_attn_out, cudaFuncAttributeMaxDynamicSharedMemorySize, AT_SMEM);

    const int nblk = (N_PTS + 127) / 128;   // 782
    k_prep<<<1, 128>>>(codebook, W_choice);
    k_prepW<<<NCOLS, 128>>>(W_q, W_v, W_out);
    k_gemm1<<<nblk, 128, G1_SMEM>>>(x, coords, W_pos, b_pos, v_gamma, v_beta);
    k_qchoice<<<N_PTS / 8, 256>>>(q_gamma, q_beta, b_choice, nbr_idx, nbr_mask);
    k_attn_out<<<nblk, 128, AT_SMEM>>>(x, out_gamma, out_beta, nbr_idx, nbr_mask, out);
}

// round 13
// speedup vs baseline: 2.7763x; 1.1477x over previous
#include <cuda_runtime.h>
#include <cuda_fp16.h>
#include <math.h>
#include <stdint.h>

#define N_PTS  100000
#define PLANES 128
#define VEC    16
#define KOFF   27
#define NCH    432
#define NCHP   448        // padded 28*16 cols
#define NCOLS  704        // 448 (W_q) + 128 (W_v) + 128 (W_out)

__device__ __forceinline__ float to_tf32(float f) {
    float r;
    asm("cvt.rna.tf32.f32 %0, %1;" : "=f"(r) : "f"(f));
    return r;
}

#define MMA_TF32_16x8x8(d, a, b) \
    asm volatile( \
        "mma.sync.aligned.m16n8k8.row.col.f32.tf32.tf32.f32 " \
        "{%0,%1,%2,%3}, {%4,%5,%6,%7}, {%8,%9}, {%0,%1,%2,%3};" \
        : "+f"((d)[0]), "+f"((d)[1]), "+f"((d)[2]), "+f"((d)[3]) \
        : "r"((a)[0]), "r"((a)[1]), "r"((a)[2]), "r"((a)[3]), \
          "r"((b)[0]), "r"((b)[1]))

// Scratch (__device__ globals: allocation-free rule)
__device__ __half g_yh[(size_t)N_PTS * NCHP];     // 89.6 MB (fp16)
__device__ float  g_choice[N_PTS];
__device__ __half g_vfh[(size_t)N_PTS * PLANES];  // 25.6 MB (fp16)
__device__ float  g_A[VEC * PLANES];
__device__ float  g_csum;
__device__ float  g_Wt[NCOLS * PLANES];           // all weights, transposed, tf32

// ---------------------------------------------------------------------------
// Kernel 0a: fold codebook into W_choice:  A[v][c], and csum = ||codebook||^2
// ---------------------------------------------------------------------------
__global__ void k_prep(const float* __restrict__ codebook,
                       const float* __restrict__ W_choice)
{
    const int c = threadIdx.x;   // 128 threads
    for (int v = 0; v < VEC; v++) {
        float s = 0.f;
#pragma unroll
        for (int j = 0; j < 8; j++) {
            const int jj = v * 8 + j;
            s = fmaf(__ldg(codebook + jj), __ldg(W_choice + jj * PLANES + c), s);
        }
        g_A[v * PLANES + c] = s;
    }
    if (c == 0) {
        float cs = 0.f;
        for (int j = 0; j < PLANES; j++) { float t = __ldg(codebook + j); cs = fmaf(t, t, cs); }
        g_csum = cs;
    }
}

// ---------------------------------------------------------------------------
// Kernel 0b: combined weight transpose -> g_Wt[col][j], tf32-rounded.
// ---------------------------------------------------------------------------
__global__ void k_prepW(const float* __restrict__ W_q,
                        const float* __restrict__ W_v,
                        const float* __restrict__ W_out)
{
    const int col = blockIdx.x;   // 0..703
    const int j   = threadIdx.x;  // 0..127
    float v = 0.f;
    if (col < NCHP) {
        if (col < NCH) {
            const int k = col >> 4, vv = col & 15;
            v = __ldg(W_q + (size_t)k * PLANES * VEC + j * VEC + vv);
        }
    } else if (col < NCHP + PLANES) {
        v = __ldg(W_v + j * PLANES + (col - NCHP));
    } else {
        v = __ldg(W_out + j * PLANES + (col - NCHP - PLANES));
    }
    g_Wt[col * PLANES + j] = to_tf32(v);
}

// ---------------------------------------------------------------------------
// Kernel 1: fused tf32 mma GEMM over 9 N-tiles of 64:
//   tiles 0..6 : y[n, col] -> g_yh (fp16)
//   tiles 7..8 : v_f[n, c] = relu((x@W_v)*g+b)+pos -> g_vfh (fp16)
// ---------------------------------------------------------------------------
#define G1_SMEM ((PLANES * 132 + 64 * 132 + PLANES * 17) * 4)

__global__ __launch_bounds__(128) void k_gemm1(
    const float* __restrict__ x, const float* __restrict__ coords,
    const float* __restrict__ W_pos, const float* __restrict__ b_pos,
    const float* __restrict__ v_gamma, const float* __restrict__ v_beta)
{
    extern __shared__ float sm[];
    float* sX   = sm;                             // 128 * 132
    float* sB   = sm + PLANES * 132;              // 64 * 132
    float* sPos = sm + PLANES * 132 + 64 * 132;   // 128 * 17

    const int tid  = threadIdx.x;
    const int wid  = tid >> 5, lane = tid & 31;
    const int g    = lane >> 2, t4 = lane & 3;
    const int n0   = blockIdx.x * 128;

    // ---- stage A tile (tf32-rounded)
    for (int it = 0; it < 32; it++) {
        const int id = it * 128 + tid;
        const int p = id >> 5, c4 = id & 31;
        const int n = n0 + p;
        float4 v = make_float4(0.f, 0.f, 0.f, 0.f);
        if (n < N_PTS) v = __ldg((const float4*)(x + (size_t)n * PLANES) + c4);
        v.x = to_tf32(v.x); v.y = to_tf32(v.y); v.z = to_tf32(v.z); v.w = to_tf32(v.w);
        *(float4*)&sX[p * 132 + c4 * 4] = v;
    }
    // ---- positional encodings: sPos[row][grp]
    {
        const int n = n0 + tid;
        float c0 = 0.f, c1 = 0.f, c2 = 0.f;
        if (n < N_PTS) {
            c0 = __ldg(coords + n * 3 + 0);
            c1 = __ldg(coords + n * 3 + 1);
            c2 = __ldg(coords + n * 3 + 2);
        }
#pragma unroll
        for (int gr = 0; gr < VEC; gr++) {
            sPos[tid * 17 + gr] =
                fmaf(c0, __ldg(W_pos + gr),
                fmaf(c1, __ldg(W_pos + VEC + gr),
                fmaf(c2, __ldg(W_pos + 2 * VEC + gr), __ldg(b_pos + gr))));
        }
    }

    const uint32_t* uX = (const uint32_t*)sX;
    const uint32_t* uB = (const uint32_t*)sB;
    const int rb = wid * 32;

    for (int tile = 0; tile < 9; tile++) {
        __syncthreads();
        for (int it = 0; it < 16; it++) {
            const int id = it * 128 + tid;
            const int r = id >> 5, c4 = id & 31;
            *(float4*)&sB[r * 132 + c4 * 4] =
                __ldg((const float4*)(g_Wt + (size_t)(tile * 64 + r) * PLANES) + c4);
        }
        __syncthreads();

        float acc[2][8][4];
#pragma unroll
        for (int mf = 0; mf < 2; mf++)
#pragma unroll
            for (int nf = 0; nf < 8; nf++)
#pragma unroll
                for (int q = 0; q < 4; q++) acc[mf][nf][q] = 0.f;

#pragma unroll 2
        for (int kb = 0; kb < 16; kb++) {
            const int k0 = kb * 8;
            uint32_t a[2][4];
#pragma unroll
            for (int mf = 0; mf < 2; mf++) {
                const int row = rb + mf * 16;
                a[mf][0] = uX[(row + g    ) * 132 + k0 + t4    ];
                a[mf][1] = uX[(row + g + 8) * 132 + k0 + t4    ];
                a[mf][2] = uX[(row + g    ) * 132 + k0 + t4 + 4];
                a[mf][3] = uX[(row + g + 8) * 132 + k0 + t4 + 4];
            }
            uint32_t b[8][2];
#pragma unroll
            for (int nf = 0; nf < 8; nf++) {
                b[nf][0] = uB[(nf * 8 + g) * 132 + k0 + t4    ];
                b[nf][1] = uB[(nf * 8 + g) * 132 + k0 + t4 + 4];
            }
#pragma unroll
            for (int mf = 0; mf < 2; mf++)
#pragma unroll
                for (int nf = 0; nf < 8; nf++)
                    MMA_TF32_16x8x8(acc[mf][nf], a[mf], b[nf]);
        }

        if (tile < 7) {
#pragma unroll
            for (int mf = 0; mf < 2; mf++) {
                const int r0 = n0 + rb + mf * 16 + g;
                const int r1 = r0 + 8;
#pragma unroll
                for (int nf = 0; nf < 8; nf++) {
                    const int col = tile * 64 + nf * 8 + t4 * 2;
                    if (r0 < N_PTS)
                        *(__half2*)(g_yh + (size_t)r0 * NCHP + col) =
                            __floats2half2_rn(acc[mf][nf][0], acc[mf][nf][1]);
                    if (r1 < N_PTS)
                        *(__half2*)(g_yh + (size_t)r1 * NCHP + col) =
                            __floats2half2_rn(acc[mf][nf][2], acc[mf][nf][3]);
                }
            }
        } else {
            const int cb = (tile - 7) * 64;
#pragma unroll
            for (int mf = 0; mf < 2; mf++) {
                const int rl0 = rb + mf * 16 + g;
                const int rl1 = rl0 + 8;
                const int r0 = n0 + rl0, r1 = n0 + rl1;
#pragma unroll
                for (int nf = 0; nf < 8; nf++) {
                    const int col = cb + nf * 8 + t4 * 2;
                    const float gm0 = __ldg(v_gamma + col),     bt0 = __ldg(v_beta + col);
                    const float gm1 = __ldg(v_gamma + col + 1), bt1 = __ldg(v_beta + col + 1);
                    const int grp = col >> 3;
                    if (r0 < N_PTS) {
                        const float pos = sPos[rl0 * 17 + grp];
                        const float o0 = fmaxf(fmaf(acc[mf][nf][0], gm0, bt0), 0.f) + pos;
                        const float o1 = fmaxf(fmaf(acc[mf][nf][1], gm1, bt1), 0.f) + pos;
                        *(__half2*)(g_vfh + (size_t)r0 * PLANES + col) = __floats2half2_rn(o0, o1);
                    }
                    if (r1 < N_PTS) {
                        const float pos = sPos[rl1 * 17 + grp];
                        const float o0 = fmaxf(fmaf(acc[mf][nf][2], gm0, bt0), 0.f) + pos;
                        const float o1 = fmaxf(fmaf(acc[mf][nf][3], gm1, bt1), 0.f) + pos;
                        *(__half2*)(g_vfh + (size_t)r1 * PLANES + col) = __floats2half2_rn(o0, o1);
                    }
                }
            }
        }
    }
}

// ---------------------------------------------------------------------------
// Kernel 2: 4 points per warp (8-lane groups). Gather fp16 y (32B = 1 sector
// per point-offset), then choice matvec partitioned c = h + 8j, group reduce.
// Block = 256 thr = 8 warps = 32 points; grid = 3125 (exact).
// ---------------------------------------------------------------------------
__global__ __launch_bounds__(256) void k_qchoice(
    const float* __restrict__ q_gamma, const float* __restrict__ q_beta,
    const float* __restrict__ b_choice,
    const int* __restrict__ nbr_idx, const int* __restrict__ nbr_mask)
{
    __shared__ float sA[VEC * PLANES];
    __shared__ int sIdx[KOFF][32];
    __shared__ int sMsk[KOFF][32];

    const int tid = threadIdx.x, lane = tid & 31, wid = tid >> 5;
    const int nb0 = blockIdx.x * 32;

    for (int i = tid; i < VEC * PLANES / 4; i += 256)
        ((float4*)sA)[i] = __ldg((const float4*)g_A + i);
    for (int i = tid; i < KOFF * 32; i += 256) {
        const int k = i >> 5, p = i & 31;
        sIdx[k][p] = __ldg(nbr_idx  + k * N_PTS + nb0 + p);
        sMsk[k][p] = __ldg(nbr_mask + k * N_PTS + nb0 + p);
    }
    __syncthreads();

    const int g3 = lane >> 3, h = lane & 7;
    const int pl = wid * 4 + g3;              // local point 0..31

    float2 acc = make_float2(0.f, 0.f);
#pragma unroll
    for (int k = 0; k < KOFF; k++) {
        const int id = sIdx[k][pl];
        const int m  = sMsk[k][pl];
        if (m) {
            const __half2 t = __ldg((const __half2*)(g_yh + (size_t)id * NCHP + k * VEC) + h);
            const float2 f = __half22float2(t);
            acc.x += f.x; acc.y += f.y;
        }
    }
    float2 qf;
    qf.x = fmaxf(fmaf(acc.x, __ldg(q_gamma + 2*h    ), __ldg(q_beta + 2*h    )), 0.f);
    qf.y = fmaxf(fmaf(acc.y, __ldg(q_gamma + 2*h + 1), __ldg(q_beta + 2*h + 1)), 0.f);

    // broadcast all 16 qf values within the 8-lane group
    float qv[16];
#pragma unroll
    for (int hh = 0; hh < 8; hh++) {
        const int src = g3 * 8 + hh;
        qv[2*hh]     = __shfl_sync(0xffffffffu, qf.x, src);
        qv[2*hh + 1] = __shfl_sync(0xffffffffu, qf.y, src);
    }

    // matvec: lane handles channels c = h + 8j (conflict-free LDS)
    float tot = 0.f;
#pragma unroll
    for (int j = 0; j < 16; j++) {
        const int c = h + 8 * j;
        float s = __ldg(b_choice + c);
#pragma unroll
        for (int v = 0; v < VEC; v++)
            s = fmaf(qv[v], sA[v * PLANES + c], s);
        tot += fmaxf(s, 0.f);
    }
#pragma unroll
    for (int off = 4; off > 0; off >>= 1)
        tot += __shfl_xor_sync(0xffffffffu, tot, off);
    if (h == 0) g_choice[nb0 + pl] = tot;
}

// ---------------------------------------------------------------------------
// Kernel 3: per 128-pt tile: warp softmax + fp16 v_f gather-aggregate into
//           sAgg (tf32), then tf32 mma GEMM out = relu((agg@W_out)*g+b) + x.
// ---------------------------------------------------------------------------
#define AT_SMEM ((PLANES * 132 + 64 * 132) * 4)

__global__ __launch_bounds__(128) void k_attn_out(
    const float* __restrict__ x,
    const float* __restrict__ out_gamma, const float* __restrict__ out_beta,
    const int* __restrict__ nbr_idx, const int* __restrict__ nbr_mask,
    float* __restrict__ out)
{
    extern __shared__ float sm[];
    float* sAgg = sm;                 // 128 * 132
    float* sB   = sm + PLANES * 132;  // 64 * 132

    const int tid = threadIdx.x;
    const int wid = tid >> 5, lane = tid & 31;
    const int g   = lane >> 2, t4 = lane & 3;
    const int n0  = blockIdx.x * 128;
    const float csum = g_csum;

    // ---- phase A: each warp aggregates 32 points
#pragma unroll 1
    for (int pp = 0; pp < 32; pp++) {
        const int pl = wid * 32 + pp;
        const int n  = n0 + pl;
        if (n >= N_PTS) {
            *(float4*)&sAgg[pl * 132 + lane * 4] = make_float4(0.f, 0.f, 0.f, 0.f);
            continue;
        }
        const float chn = __ldg(g_choice + n);
        int idxv = 0, mk = 0;
        if (lane < KOFF) {
            idxv = __ldg(nbr_idx  + lane * N_PTS + n);
            mk   = __ldg(nbr_mask + lane * N_PTS + n);
        }
        float s = (mk != 0) ? chn * __ldg(g_choice + idxv) * csum : -3.0e38f;
        float mx = s;
#pragma unroll
        for (int off = 16; off > 0; off >>= 1)
            mx = fmaxf(mx, __shfl_xor_sync(0xffffffffu, mx, off));
        const float e = (mk != 0) ? __expf(s - mx) : 0.f;
        float den = e;
#pragma unroll
        for (int off = 16; off > 0; off >>= 1)
            den += __shfl_xor_sync(0xffffffffu, den, off);
        const float rd = 1.0f / den;

        float ax = 0.f, ay = 0.f, az = 0.f, aw2 = 0.f;
#pragma unroll
        for (int k0 = 0; k0 < KOFF; k0 += 9) {
            float wk[9]; int ik[9];
#pragma unroll
            for (int q = 0; q < 9; q++) {
                wk[q] = __shfl_sync(0xffffffffu, e,    k0 + q);
                ik[q] = __shfl_sync(0xffffffffu, idxv, k0 + q);
            }
            uint2 t[9];
#pragma unroll
            for (int q = 0; q < 9; q++) {
                t[q] = make_uint2(0u, 0u);
                if (wk[q] != 0.f)
                    t[q] = __ldg((const uint2*)(g_vfh + (size_t)ik[q] * PLANES) + lane);
            }
#pragma unroll
            for (int q = 0; q < 9; q++) {
                const float2 fa = __half22float2(*(__half2*)&t[q].x);
                const float2 fb = __half22float2(*(__half2*)&t[q].y);
                ax  = fmaf(wk[q], fa.x, ax);
                ay  = fmaf(wk[q], fa.y, ay);
                az  = fmaf(wk[q], fb.x, az);
                aw2 = fmaf(wk[q], fb.y, aw2);
            }
        }
        *(float4*)&sAgg[pl * 132 + lane * 4] =
            make_float4(to_tf32(ax * rd), to_tf32(ay * rd),
                        to_tf32(az * rd), to_tf32(aw2 * rd));
    }

    // ---- phase B: 128x128 @ 128x128 tf32 mma GEMM (2 N-tiles of 64)
    const uint32_t* uX = (const uint32_t*)sAgg;
    const uint32_t* uB = (const uint32_t*)sB;
    const int rb = wid * 32;

    for (int tile = 0; tile < 2; tile++) {
        __syncthreads();
        for (int it = 0; it < 16; it++) {
            const int id = it * 128 + tid;
            const int r = id >> 5, c4 = id & 31;
            *(float4*)&sB[r * 132 + c4 * 4] =
                __ldg((const float4*)(g_Wt + (size_t)(NCHP + PLANES + tile * 64 + r) * PLANES) + c4);
        }
        __syncthreads();

        float acc[2][8][4];
#pragma unroll
        for (int mf = 0; mf < 2; mf++)
#pragma unroll
            for (int nf = 0; nf < 8; nf++)
#pragma unroll
                for (int q = 0; q < 4; q++) acc[mf][nf][q] = 0.f;

#pragma unroll 2
        for (int kb = 0; kb < 16; kb++) {
            const int k0 = kb * 8;
            uint32_t a[2][4];
#pragma unroll
            for (int mf = 0; mf < 2; mf++) {
                const int row = rb + mf * 16;
                a[mf][0] = uX[(row + g    ) * 132 + k0 + t4    ];
                a[mf][1] = uX[(row + g + 8) * 132 + k0 + t4    ];
                a[mf][2] = uX[(row + g    ) * 132 + k0 + t4 + 4];
                a[mf][3] = uX[(row + g + 8) * 132 + k0 + t4 + 4];
            }
            uint32_t b[8][2];
#pragma unroll
            for (int nf = 0; nf < 8; nf++) {
                b[nf][0] = uB[(nf * 8 + g) * 132 + k0 + t4    ];
                b[nf][1] = uB[(nf * 8 + g) * 132 + k0 + t4 + 4];
            }
#pragma unroll
            for (int mf = 0; mf < 2; mf++)
#pragma unroll
                for (int nf = 0; nf < 8; nf++)
                    MMA_TF32_16x8x8(acc[mf][nf], a[mf], b[nf]);
        }

#pragma unroll
        for (int mf = 0; mf < 2; mf++) {
            const int r0 = n0 + rb + mf * 16 + g;
            const int r1 = r0 + 8;
#pragma unroll
            for (int nf = 0; nf < 8; nf++) {
                const int col = tile * 64 + nf * 8 + t4 * 2;
                const float gm0 = __ldg(out_gamma + col),     bt0 = __ldg(out_beta + col);
                const float gm1 = __ldg(out_gamma + col + 1), bt1 = __ldg(out_beta + col + 1);
                if (r0 < N_PTS) {
                    const float2 xv = __ldg((const float2*)(x + (size_t)r0 * PLANES + col));
                    const float o0 = fmaxf(fmaf(acc[mf][nf][0], gm0, bt0), 0.f) + xv.x;
                    const float o1 = fmaxf(fmaf(acc[mf][nf][1], gm1, bt1), 0.f) + xv.y;
                    *(float2*)(out + (size_t)r0 * PLANES + col) = make_float2(o0, o1);
                }
                if (r1 < N_PTS) {
                    const float2 xv = __ldg((const float2*)(x + (size_t)r1 * PLANES + col));
                    const float o0 = fmaxf(fmaf(acc[mf][nf][2], gm0, bt0), 0.f) + xv.x;
                    const float o1 = fmaxf(fmaf(acc[mf][nf][3], gm1, bt1), 0.f) + xv.y;
                    *(float2*)(out + (size_t)r1 * PLANES + col) = make_float2(o0, o1);
                }
            }
        }
    }
}

// ---------------------------------------------------------------------------
extern "C" void kernel_launch(void* const* d_in, const int* in_sizes, int n_in,
                              void* d_out, int out_size)
{
    const float* x         = (const float*)d_in[0];
    const float* coords    = (const float*)d_in[1];
    const float* W_q       = (const float*)d_in[2];
    const float* q_gamma   = (const float*)d_in[3];
    const float* q_beta    = (const float*)d_in[4];
    const float* W_v       = (const float*)d_in[5];
    const float* v_gamma   = (const float*)d_in[6];
    const float* v_beta    = (const float*)d_in[7];
    const float* codebook  = (const float*)d_in[8];
    const float* W_choice  = (const float*)d_in[9];
    const float* b_choice  = (const float*)d_in[10];
    const float* W_pos     = (const float*)d_in[11];
    const float* b_pos     = (const float*)d_in[12];
    const float* W_out     = (const float*)d_in[13];
    const float* out_gamma = (const float*)d_in[14];
    const float* out_beta  = (const float*)d_in[15];
    const int*   nbr_idx   = (const int*)d_in[16];
    const int*   nbr_mask  = (const int*)d_in[17];
    float* out = (float*)d_out;

    cudaFuncSetAttribute(k_gemm1,    cudaFuncAttributeMaxDynamicSharedMemorySize, G1_SMEM);
    cudaFuncSetAttribute(k_attn_out, cudaFuncAttributeMaxDynamicSharedMemorySize, AT_SMEM);

    const int nblk = (N_PTS + 127) / 128;   // 782
    k_prep<<<1, 128>>>(codebook, W_choice);
    k_prepW<<<NCOLS, 128>>>(W_q, W_v, W_out);
    k_gemm1<<<nblk, 128, G1_SMEM>>>(x, coords, W_pos, b_pos, v_gamma, v_beta);
    k_qchoice<<<N_PTS / 32, 256>>>(q_gamma, q_beta, b_choice, nbr_idx, nbr_mask);
    k_attn_out<<<nblk, 128, AT_SMEM>>>(x, out_gamma, out_beta, nbr_idx, nbr_mask, out);
}

// round 14
// speedup vs baseline: 3.1817x; 1.1460x over previous
#include <cuda_runtime.h>
#include <cuda_fp16.h>
#include <math.h>
#include <stdint.h>

#define N_PTS  100000
#define PLANES 128
#define VEC    16
#define KOFF   27
#define NCH    432
#define NCHP   448        // padded 28*16 cols
#define NCOLS  704        // 448 (W_q) + 128 (W_v) + 128 (W_out)

__device__ __forceinline__ float to_tf32(float f) {
    float r;
    asm("cvt.rna.tf32.f32 %0, %1;" : "=f"(r) : "f"(f));
    return r;
}

#define MMA_TF32_16x8x8(d, a, b) \
    asm volatile( \
        "mma.sync.aligned.m16n8k8.row.col.f32.tf32.tf32.f32 " \
        "{%0,%1,%2,%3}, {%4,%5,%6,%7}, {%8,%9}, {%0,%1,%2,%3};" \
        : "+f"((d)[0]), "+f"((d)[1]), "+f"((d)[2]), "+f"((d)[3]) \
        : "r"((a)[0]), "r"((a)[1]), "r"((a)[2]), "r"((a)[3]), \
          "r"((b)[0]), "r"((b)[1]))

// Scratch (__device__ globals: allocation-free rule)
__device__ __half g_yh[(size_t)N_PTS * NCHP];     // 89.6 MB (fp16)
__device__ float  g_choice[N_PTS];
__device__ __half g_vfh[(size_t)N_PTS * PLANES];  // 25.6 MB (fp16)
__device__ float  g_aw[(size_t)N_PTS * 28];       // 11.2 MB normalized attn weights
__device__ float  g_A[VEC * PLANES];
__device__ float  g_csum;
__device__ float  g_Wt[NCOLS * PLANES];           // all weights, transposed, tf32

// ---------------------------------------------------------------------------
// Kernel 0a: fold codebook into W_choice:  A[v][c], and csum = ||codebook||^2
// ---------------------------------------------------------------------------
__global__ void k_prep(const float* __restrict__ codebook,
                       const float* __restrict__ W_choice)
{
    const int c = threadIdx.x;   // 128 threads
    for (int v = 0; v < VEC; v++) {
        float s = 0.f;
#pragma unroll
        for (int j = 0; j < 8; j++) {
            const int jj = v * 8 + j;
            s = fmaf(__ldg(codebook + jj), __ldg(W_choice + jj * PLANES + c), s);
        }
        g_A[v * PLANES + c] = s;
    }
    if (c == 0) {
        float cs = 0.f;
        for (int j = 0; j < PLANES; j++) { float t = __ldg(codebook + j); cs = fmaf(t, t, cs); }
        g_csum = cs;
    }
}

// ---------------------------------------------------------------------------
// Kernel 0b: combined weight transpose -> g_Wt[col][j], tf32-rounded.
// ---------------------------------------------------------------------------
__global__ void k_prepW(const float* __restrict__ W_q,
                        const float* __restrict__ W_v,
                        const float* __restrict__ W_out)
{
    const int col = blockIdx.x;   // 0..703
    const int j   = threadIdx.x;  // 0..127
    float v = 0.f;
    if (col < NCHP) {
        if (col < NCH) {
            const int k = col >> 4, vv = col & 15;
            v = __ldg(W_q + (size_t)k * PLANES * VEC + j * VEC + vv);
        }
    } else if (col < NCHP + PLANES) {
        v = __ldg(W_v + j * PLANES + (col - NCHP));
    } else {
        v = __ldg(W_out + j * PLANES + (col - NCHP - PLANES));
    }
    g_Wt[col * PLANES + j] = to_tf32(v);
}

// ---------------------------------------------------------------------------
// Kernel 1: fused tf32 mma GEMM over 9 N-tiles of 64 (256 thr, M-tile 128):
//   tiles 0..6 : y[n, col] -> g_yh (fp16)
//   tiles 7..8 : v_f[n, c] = relu((x@W_v)*g+b)+pos -> g_vfh (fp16)
// ---------------------------------------------------------------------------
#define G1_SMEM ((PLANES * 132 + 64 * 132 + PLANES * 17) * 4)

__global__ __launch_bounds__(256) void k_gemm1(
    const float* __restrict__ x, const float* __restrict__ coords,
    const float* __restrict__ W_pos, const float* __restrict__ b_pos,
    const float* __restrict__ v_gamma, const float* __restrict__ v_beta)
{
    extern __shared__ float sm[];
    float* sX   = sm;                             // 128 * 132
    float* sB   = sm + PLANES * 132;              // 64 * 132
    float* sPos = sm + PLANES * 132 + 64 * 132;   // 128 * 17

    const int tid  = threadIdx.x;
    const int wid  = tid >> 5, lane = tid & 31;
    const int g    = lane >> 2, t4 = lane & 3;
    const int n0   = blockIdx.x * 128;
    const int rb   = wid * 16;                    // warp row base (8 warps)

    // ---- stage A tile (tf32-rounded)
    for (int it = 0; it < 16; it++) {
        const int id = it * 256 + tid;
        const int p = id >> 5, c4 = id & 31;
        const int n = n0 + p;
        float4 v = make_float4(0.f, 0.f, 0.f, 0.f);
        if (n < N_PTS) v = __ldg((const float4*)(x + (size_t)n * PLANES) + c4);
        v.x = to_tf32(v.x); v.y = to_tf32(v.y); v.z = to_tf32(v.z); v.w = to_tf32(v.w);
        *(float4*)&sX[p * 132 + c4 * 4] = v;
    }
    // ---- positional encodings: sPos[row][grp]
    if (tid < 128) {
        const int n = n0 + tid;
        float c0 = 0.f, c1 = 0.f, c2 = 0.f;
        if (n < N_PTS) {
            c0 = __ldg(coords + n * 3 + 0);
            c1 = __ldg(coords + n * 3 + 1);
            c2 = __ldg(coords + n * 3 + 2);
        }
#pragma unroll
        for (int gr = 0; gr < VEC; gr++) {
            sPos[tid * 17 + gr] =
                fmaf(c0, __ldg(W_pos + gr),
                fmaf(c1, __ldg(W_pos + VEC + gr),
                fmaf(c2, __ldg(W_pos + 2 * VEC + gr), __ldg(b_pos + gr))));
        }
    }

    const uint32_t* uX = (const uint32_t*)sX;
    const uint32_t* uB = (const uint32_t*)sB;

    for (int tile = 0; tile < 9; tile++) {
        __syncthreads();
        for (int it = 0; it < 8; it++) {
            const int id = it * 256 + tid;
            const int r = id >> 5, c4 = id & 31;
            *(float4*)&sB[r * 132 + c4 * 4] =
                __ldg((const float4*)(g_Wt + (size_t)(tile * 64 + r) * PLANES) + c4);
        }
        __syncthreads();

        float acc[8][4];
#pragma unroll
        for (int nf = 0; nf < 8; nf++)
#pragma unroll
            for (int q = 0; q < 4; q++) acc[nf][q] = 0.f;

#pragma unroll 2
        for (int kb = 0; kb < 16; kb++) {
            const int k0 = kb * 8;
            uint32_t a[4];
            a[0] = uX[(rb + g    ) * 132 + k0 + t4    ];
            a[1] = uX[(rb + g + 8) * 132 + k0 + t4    ];
            a[2] = uX[(rb + g    ) * 132 + k0 + t4 + 4];
            a[3] = uX[(rb + g + 8) * 132 + k0 + t4 + 4];
            uint32_t b[8][2];
#pragma unroll
            for (int nf = 0; nf < 8; nf++) {
                b[nf][0] = uB[(nf * 8 + g) * 132 + k0 + t4    ];
                b[nf][1] = uB[(nf * 8 + g) * 132 + k0 + t4 + 4];
            }
#pragma unroll
            for (int nf = 0; nf < 8; nf++)
                MMA_TF32_16x8x8(acc[nf], a, b[nf]);
        }

        if (tile < 7) {
            const int r0 = n0 + rb + g;
            const int r1 = r0 + 8;
#pragma unroll
            for (int nf = 0; nf < 8; nf++) {
                const int col = tile * 64 + nf * 8 + t4 * 2;
                if (r0 < N_PTS)
                    *(__half2*)(g_yh + (size_t)r0 * NCHP + col) =
                        __floats2half2_rn(acc[nf][0], acc[nf][1]);
                if (r1 < N_PTS)
                    *(__half2*)(g_yh + (size_t)r1 * NCHP + col) =
                        __floats2half2_rn(acc[nf][2], acc[nf][3]);
            }
        } else {
            const int cb = (tile - 7) * 64;
            const int rl0 = rb + g, rl1 = rl0 + 8;
            const int r0 = n0 + rl0, r1 = n0 + rl1;
#pragma unroll
            for (int nf = 0; nf < 8; nf++) {
                const int col = cb + nf * 8 + t4 * 2;
                const float gm0 = __ldg(v_gamma + col),     bt0 = __ldg(v_beta + col);
                const float gm1 = __ldg(v_gamma + col + 1), bt1 = __ldg(v_beta + col + 1);
                const int grp = col >> 3;
                if (r0 < N_PTS) {
                    const float pos = sPos[rl0 * 17 + grp];
                    const float o0 = fmaxf(fmaf(acc[nf][0], gm0, bt0), 0.f) + pos;
                    const float o1 = fmaxf(fmaf(acc[nf][1], gm1, bt1), 0.f) + pos;
                    *(__half2*)(g_vfh + (size_t)r0 * PLANES + col) = __floats2half2_rn(o0, o1);
                }
                if (r1 < N_PTS) {
                    const float pos = sPos[rl1 * 17 + grp];
                    const float o0 = fmaxf(fmaf(acc[nf][2], gm0, bt0), 0.f) + pos;
                    const float o1 = fmaxf(fmaf(acc[nf][3], gm1, bt1), 0.f) + pos;
                    *(__half2*)(g_vfh + (size_t)r1 * PLANES + col) = __floats2half2_rn(o0, o1);
                }
            }
        }
    }
}

// ---------------------------------------------------------------------------
// Kernel 2: 4 points per warp (8-lane groups). Gather fp16 y (32B = 1 sector
// per point-offset), then choice matvec partitioned c = h + 8j, group reduce.
// ---------------------------------------------------------------------------
__global__ __launch_bounds__(256) void k_qchoice(
    const float* __restrict__ q_gamma, const float* __restrict__ q_beta,
    const float* __restrict__ b_choice,
    const int* __restrict__ nbr_idx, const int* __restrict__ nbr_mask)
{
    __shared__ float sA[VEC * PLANES];
    __shared__ int sIdx[KOFF][32];
    __shared__ int sMsk[KOFF][32];

    const int tid = threadIdx.x, lane = tid & 31, wid = tid >> 5;
    const int nb0 = blockIdx.x * 32;

    for (int i = tid; i < VEC * PLANES / 4; i += 256)
        ((float4*)sA)[i] = __ldg((const float4*)g_A + i);
    for (int i = tid; i < KOFF * 32; i += 256) {
        const int k = i >> 5, p = i & 31;
        sIdx[k][p] = __ldg(nbr_idx  + k * N_PTS + nb0 + p);
        sMsk[k][p] = __ldg(nbr_mask + k * N_PTS + nb0 + p);
    }
    __syncthreads();

    const int g3 = lane >> 3, h = lane & 7;
    const int pl = wid * 4 + g3;              // local point 0..31

    float2 acc = make_float2(0.f, 0.f);
#pragma unroll
    for (int k = 0; k < KOFF; k++) {
        const int id = sIdx[k][pl];
        const int m  = sMsk[k][pl];
        if (m) {
            const __half2 t = __ldg((const __half2*)(g_yh + (size_t)id * NCHP + k * VEC) + h);
            const float2 f = __half22float2(t);
            acc.x += f.x; acc.y += f.y;
        }
    }
    float2 qf;
    qf.x = fmaxf(fmaf(acc.x, __ldg(q_gamma + 2*h    ), __ldg(q_beta + 2*h    )), 0.f);
    qf.y = fmaxf(fmaf(acc.y, __ldg(q_gamma + 2*h + 1), __ldg(q_beta + 2*h + 1)), 0.f);

    float qv[16];
#pragma unroll
    for (int hh = 0; hh < 8; hh++) {
        const int src = g3 * 8 + hh;
        qv[2*hh]     = __shfl_sync(0xffffffffu, qf.x, src);
        qv[2*hh + 1] = __shfl_sync(0xffffffffu, qf.y, src);
    }

    float tot = 0.f;
#pragma unroll
    for (int j = 0; j < 16; j++) {
        const int c = h + 8 * j;
        float s = __ldg(b_choice + c);
#pragma unroll
        for (int v = 0; v < VEC; v++)
            s = fmaf(qv[v], sA[v * PLANES + c], s);
        tot += fmaxf(s, 0.f);
    }
#pragma unroll
    for (int off = 4; off > 0; off >>= 1)
        tot += __shfl_xor_sync(0xffffffffu, tot, off);
    if (h == 0) g_choice[nb0 + pl] = tot;
}

// ---------------------------------------------------------------------------
// Kernel 2b: normalized attention weights. Warp per point, no smem ->
//            full occupancy; removes softmax chain from the attn kernel.
// ---------------------------------------------------------------------------
__global__ __launch_bounds__(256) void k_attw(
    const int* __restrict__ nbr_idx, const int* __restrict__ nbr_mask)
{
    const int tid = threadIdx.x, lane = tid & 31, wid = tid >> 5;
    const int n = blockIdx.x * 8 + wid;    // grid = 12500 -> exactly N_PTS warps
    const float csum = g_csum;
    const float chn = __ldg(g_choice + n);

    int idxv = 0, mk = 0;
    if (lane < KOFF) {
        idxv = __ldg(nbr_idx  + lane * N_PTS + n);
        mk   = __ldg(nbr_mask + lane * N_PTS + n);
    }
    float s = (mk != 0) ? chn * __ldg(g_choice + idxv) * csum : -3.0e38f;
    float mx = s;
#pragma unroll
    for (int off = 16; off > 0; off >>= 1)
        mx = fmaxf(mx, __shfl_xor_sync(0xffffffffu, mx, off));
    const float e = (mk != 0) ? __expf(s - mx) : 0.f;
    float den = e;
#pragma unroll
    for (int off = 16; off > 0; off >>= 1)
        den += __shfl_xor_sync(0xffffffffu, den, off);
    if (lane < KOFF) g_aw[(size_t)n * 28 + lane] = e / den;
}

// ---------------------------------------------------------------------------
// Kernel 3 (256 thr): phase A: 8 warps x 16 points, gather fp16 v_f with
// precomputed weights into sAgg (tf32); phase B: tf32 mma out-projection.
// ---------------------------------------------------------------------------
#define AT_SMEM ((PLANES * 132 + 64 * 132) * 4)

__global__ __launch_bounds__(256) void k_attn_out(
    const float* __restrict__ x,
    const float* __restrict__ out_gamma, const float* __restrict__ out_beta,
    const int* __restrict__ nbr_idx,
    float* __restrict__ out)
{
    extern __shared__ float sm[];
    float* sAgg = sm;                 // 128 * 132
    float* sB   = sm + PLANES * 132;  // 64 * 132

    const int tid = threadIdx.x;
    const int wid = tid >> 5, lane = tid & 31;
    const int g   = lane >> 2, t4 = lane & 3;
    const int n0  = blockIdx.x * 128;
    const int rb  = wid * 16;

    // ---- phase A: each warp aggregates 16 points
#pragma unroll 1
    for (int pp = 0; pp < 16; pp++) {
        const int pl = wid * 16 + pp;
        const int n  = n0 + pl;
        if (n >= N_PTS) {
            *(float4*)&sAgg[pl * 132 + lane * 4] = make_float4(0.f, 0.f, 0.f, 0.f);
            continue;
        }
        float wkf = 0.f;
        int idxv = 0;
        if (lane < KOFF) {
            wkf  = __ldg(g_aw + (size_t)n * 28 + lane);
            idxv = __ldg(nbr_idx + lane * N_PTS + n);
        }

        float ax = 0.f, ay = 0.f, az = 0.f, aw2 = 0.f;
#pragma unroll
        for (int k0 = 0; k0 < KOFF; k0 += 9) {
            float wk[9]; int ik[9];
#pragma unroll
            for (int q = 0; q < 9; q++) {
                wk[q] = __shfl_sync(0xffffffffu, wkf,  k0 + q);
                ik[q] = __shfl_sync(0xffffffffu, idxv, k0 + q);
            }
            uint2 t[9];
#pragma unroll
            for (int q = 0; q < 9; q++) {
                t[q] = make_uint2(0u, 0u);
                if (wk[q] != 0.f)
                    t[q] = __ldg((const uint2*)(g_vfh + (size_t)ik[q] * PLANES) + lane);
            }
#pragma unroll
            for (int q = 0; q < 9; q++) {
                const float2 fa = __half22float2(*(__half2*)&t[q].x);
                const float2 fb = __half22float2(*(__half2*)&t[q].y);
                ax  = fmaf(wk[q], fa.x, ax);
                ay  = fmaf(wk[q], fa.y, ay);
                az  = fmaf(wk[q], fb.x, az);
                aw2 = fmaf(wk[q], fb.y, aw2);
            }
        }
        *(float4*)&sAgg[pl * 132 + lane * 4] =
            make_float4(to_tf32(ax), to_tf32(ay), to_tf32(az), to_tf32(aw2));
    }

    // ---- phase B: 128x128 @ 128x128 tf32 mma GEMM (2 N-tiles of 64)
    const uint32_t* uX = (const uint32_t*)sAgg;
    const uint32_t* uB = (const uint32_t*)sB;

    for (int tile = 0; tile < 2; tile++) {
        __syncthreads();
        for (int it = 0; it < 8; it++) {
            const int id = it * 256 + tid;
            const int r = id >> 5, c4 = id & 31;
            *(float4*)&sB[r * 132 + c4 * 4] =
                __ldg((const float4*)(g_Wt + (size_t)(NCHP + PLANES + tile * 64 + r) * PLANES) + c4);
        }
        __syncthreads();

        float acc[8][4];
#pragma unroll
        for (int nf = 0; nf < 8; nf++)
#pragma unroll
            for (int q = 0; q < 4; q++) acc[nf][q] = 0.f;

#pragma unroll 2
        for (int kb = 0; kb < 16; kb++) {
            const int k0 = kb * 8;
            uint32_t a[4];
            a[0] = uX[(rb + g    ) * 132 + k0 + t4    ];
            a[1] = uX[(rb + g + 8) * 132 + k0 + t4    ];
            a[2] = uX[(rb + g    ) * 132 + k0 + t4 + 4];
            a[3] = uX[(rb + g + 8) * 132 + k0 + t4 + 4];
            uint32_t b[8][2];
#pragma unroll
            for (int nf = 0; nf < 8; nf++) {
                b[nf][0] = uB[(nf * 8 + g) * 132 + k0 + t4    ];
                b[nf][1] = uB[(nf * 8 + g) * 132 + k0 + t4 + 4];
            }
#pragma unroll
            for (int nf = 0; nf < 8; nf++)
                MMA_TF32_16x8x8(acc[nf], a, b[nf]);
        }

        const int r0 = n0 + rb + g;
        const int r1 = r0 + 8;
#pragma unroll
        for (int nf = 0; nf < 8; nf++) {
            const int col = tile * 64 + nf * 8 + t4 * 2;
            const float gm0 = __ldg(out_gamma + col),     bt0 = __ldg(out_beta + col);
            const float gm1 = __ldg(out_gamma + col + 1), bt1 = __ldg(out_beta + col + 1);
            if (r0 < N_PTS) {
                const float2 xv = __ldg((const float2*)(x + (size_t)r0 * PLANES + col));
                const float o0 = fmaxf(fmaf(acc[nf][0], gm0, bt0), 0.f) + xv.x;
                const float o1 = fmaxf(fmaf(acc[nf][1], gm1, bt1), 0.f) + xv.y;
                *(float2*)(out + (size_t)r0 * PLANES + col) = make_float2(o0, o1);
            }
            if (r1 < N_PTS) {
                const float2 xv = __ldg((const float2*)(x + (size_t)r1 * PLANES + col));
                const float o0 = fmaxf(fmaf(acc[nf][2], gm0, bt0), 0.f) + xv.x;
                const float o1 = fmaxf(fmaf(acc[nf][3], gm1, bt1), 0.f) + xv.y;
                *(float2*)(out + (size_t)r1 * PLANES + col) = make_float2(o0, o1);
            }
        }
    }
}

// ---------------------------------------------------------------------------
extern "C" void kernel_launch(void* const* d_in, const int* in_sizes, int n_in,
                              void* d_out, int out_size)
{
    const float* x         = (const float*)d_in[0];
    const float* coords    = (const float*)d_in[1];
    const float* W_q       = (const float*)d_in[2];
    const float* q_gamma   = (const float*)d_in[3];
    const float* q_beta    = (const float*)d_in[4];
    const float* W_v       = (const float*)d_in[5];
    const float* v_gamma   = (const float*)d_in[6];
    const float* v_beta    = (const float*)d_in[7];
    const float* codebook  = (const float*)d_in[8];
    const float* W_choice  = (const float*)d_in[9];
    const float* b_choice  = (const float*)d_in[10];
    const float* W_pos     = (const float*)d_in[11];
    const float* b_pos     = (const float*)d_in[12];
    const float* W_out     = (const float*)d_in[13];
    const float* out_gamma = (const float*)d_in[14];
    const float* out_beta  = (const float*)d_in[15];
    const int*   nbr_idx   = (const int*)d_in[16];
    const int*   nbr_mask  = (const int*)d_in[17];
    float* out = (float*)d_out;

    cudaFuncSetAttribute(k_gemm1,    cudaFuncAttributeMaxDynamicSharedMemorySize, G1_SMEM);
    cudaFuncSetAttribute(k_attn_out, cudaFuncAttributeMaxDynamicSharedMemorySize, AT_SMEM);

    const int nblk = (N_PTS + 127) / 128;   // 782
    k_prep<<<1, 128>>>(codebook, W_choice);
    k_prepW<<<NCOLS, 128>>>(W_q, W_v, W_out);
    k_gemm1<<<nblk, 256, G1_SMEM>>>(x, coords, W_pos, b_pos, v_gamma, v_beta);
    k_qchoice<<<N_PTS / 32, 256>>>(q_gamma, q_beta, b_choice, nbr_idx, nbr_mask);
    k_attw<<<N_PTS / 8, 256>>>(nbr_idx, nbr_mask);
    k_attn_out<<<nblk, 256, AT_SMEM>>>(x, out_gamma, out_beta, nbr_idx, out);
}

// round 16
// speedup vs baseline: 4.2193x; 1.3261x over previous
#include <cuda_runtime.h>
#include <cuda_fp16.h>
#include <math.h>
#include <stdint.h>

#define N_PTS  100000
#define PLANES 128
#define VEC    16
#define KOFF   27
#define NCH    432
#define NCHP   448        // padded 28*16 cols
#define NCOLS  704        // 448 (W_q) + 128 (W_v) + 128 (W_out)
#define STH    136        // smem half-stride (68 words)

#define MMA_F16_16x8x16(d, a, b) \
    asm volatile( \
        "mma.sync.aligned.m16n8k16.row.col.f32.f16.f16.f32 " \
        "{%0,%1,%2,%3}, {%4,%5,%6,%7}, {%8,%9}, {%0,%1,%2,%3};" \
        : "+f"((d)[0]), "+f"((d)[1]), "+f"((d)[2]), "+f"((d)[3]) \
        : "r"((a)[0]), "r"((a)[1]), "r"((a)[2]), "r"((a)[3]), \
          "r"((b)[0]), "r"((b)[1]))

// Scratch (__device__ globals: allocation-free rule)
__device__ __half g_yh[(size_t)N_PTS * NCHP];     // 89.6 MB (fp16)
__device__ float  g_choice[N_PTS];
__device__ __half g_vfh[(size_t)N_PTS * PLANES];  // 25.6 MB (fp16)
__device__ float  g_aw[(size_t)N_PTS * 28];       // 11.2 MB normalized attn weights
__device__ float  g_A[VEC * PLANES];
__device__ float  g_csum;
__device__ __half g_Wth[NCOLS * PLANES];          // all weights, transposed, fp16

// ---------------------------------------------------------------------------
// Kernel 0a: fold codebook into W_choice:  A[v][c], and csum = ||codebook||^2
// ---------------------------------------------------------------------------
__global__ void k_prep(const float* __restrict__ codebook,
                       const float* __restrict__ W_choice)
{
    const int c = threadIdx.x;   // 128 threads
    for (int v = 0; v < VEC; v++) {
        float s = 0.f;
#pragma unroll
        for (int j = 0; j < 8; j++) {
            const int jj = v * 8 + j;
            s = fmaf(__ldg(codebook + jj), __ldg(W_choice + jj * PLANES + c), s);
        }
        g_A[v * PLANES + c] = s;
    }
    if (c == 0) {
        float cs = 0.f;
        for (int j = 0; j < PLANES; j++) { float t = __ldg(codebook + j); cs = fmaf(t, t, cs); }
        g_csum = cs;
    }
}

// ---------------------------------------------------------------------------
// Kernel 0b: combined weight transpose -> g_Wth[col][j], fp16.
// ---------------------------------------------------------------------------
__global__ void k_prepW(const float* __restrict__ W_q,
                        const float* __restrict__ W_v,
                        const float* __restrict__ W_out)
{
    const int col = blockIdx.x;   // 0..703
    const int j   = threadIdx.x;  // 0..127
    float v = 0.f;
    if (col < NCHP) {
        if (col < NCH) {
            const int k = col >> 4, vv = col & 15;
            v = __ldg(W_q + (size_t)k * PLANES * VEC + j * VEC + vv);
        }
    } else if (col < NCHP + PLANES) {
        v = __ldg(W_v + j * PLANES + (col - NCHP));
    } else {
        v = __ldg(W_out + j * PLANES + (col - NCHP - PLANES));
    }
    g_Wth[col * PLANES + j] = __float2half_rn(v);
}

// ---------------------------------------------------------------------------
// Kernel 1: fused fp16 mma GEMM over 9 N-tiles of 64 (256 thr, M-tile 128):
//   tiles 0..6 : y[n, col] -> g_yh (fp16)
//   tiles 7..8 : v_f[n, c] = relu((x@W_v)*g+b)+pos -> g_vfh (fp16)
// ---------------------------------------------------------------------------
#define G1_SMEM ((PLANES * STH + 64 * STH) * 2 + PLANES * 17 * 4)

__global__ __launch_bounds__(256) void k_gemm1(
    const float* __restrict__ x, const float* __restrict__ coords,
    const float* __restrict__ W_pos, const float* __restrict__ b_pos,
    const float* __restrict__ v_gamma, const float* __restrict__ v_beta)
{
    extern __shared__ char smraw[];
    __half* sXh  = (__half*)smraw;                          // 128 * 136 halves
    __half* sBh  = (__half*)(smraw + PLANES * STH * 2);     // 64 * 136 halves
    float*  sPos = (float*)(smraw + (PLANES + 64) * STH * 2); // 128 * 17

    const int tid  = threadIdx.x;
    const int wid  = tid >> 5, lane = tid & 31;
    const int g    = lane >> 2, t4 = lane & 3;
    const int n0   = blockIdx.x * 128;
    const int rb   = wid * 16;                    // warp row base (8 warps)

    // ---- stage A tile: float4 -> 4 halves (uint2 store)
    for (int it = 0; it < 16; it++) {
        const int id = it * 256 + tid;
        const int p = id >> 5, c4 = id & 31;
        const int n = n0 + p;
        float4 v = make_float4(0.f, 0.f, 0.f, 0.f);
        if (n < N_PTS) v = __ldg((const float4*)(x + (size_t)n * PLANES) + c4);
        __half2 h0 = __floats2half2_rn(v.x, v.y);
        __half2 h1 = __floats2half2_rn(v.z, v.w);
        *(uint2*)&sXh[p * STH + c4 * 4] = make_uint2(*(uint32_t*)&h0, *(uint32_t*)&h1);
    }
    // ---- positional encodings: sPos[row][grp]
    if (tid < 128) {
        const int n = n0 + tid;
        float c0 = 0.f, c1 = 0.f, c2 = 0.f;
        if (n < N_PTS) {
            c0 = __ldg(coords + n * 3 + 0);
            c1 = __ldg(coords + n * 3 + 1);
            c2 = __ldg(coords + n * 3 + 2);
        }
#pragma unroll
        for (int gr = 0; gr < VEC; gr++) {
            sPos[tid * 17 + gr] =
                fmaf(c0, __ldg(W_pos + gr),
                fmaf(c1, __ldg(W_pos + VEC + gr),
                fmaf(c2, __ldg(W_pos + 2 * VEC + gr), __ldg(b_pos + gr))));
        }
    }

    const uint32_t* uX = (const uint32_t*)sXh;
    const uint32_t* uB = (const uint32_t*)sBh;

    for (int tile = 0; tile < 9; tile++) {
        __syncthreads();
        // stage B tile: 64 rows x 128 halves, uint4 = 8 halves
        for (int it = 0; it < 4; it++) {
            const int id = it * 256 + tid;
            const int r = id >> 4, c16 = id & 15;
            *(uint4*)&sBh[r * STH + c16 * 8] =
                __ldg((const uint4*)(g_Wth + (size_t)(tile * 64 + r) * PLANES) + c16);
        }
        __syncthreads();

        float acc[8][4];
#pragma unroll
        for (int nf = 0; nf < 8; nf++)
#pragma unroll
            for (int q = 0; q < 4; q++) acc[nf][q] = 0.f;

#pragma unroll 2
        for (int kb = 0; kb < 8; kb++) {
            const int kw = kb * 8;   // word offset (16 halves = 8 words)
            uint32_t a[4];
            a[0] = uX[(rb + g    ) * (STH/2) + kw + t4    ];
            a[1] = uX[(rb + g + 8) * (STH/2) + kw + t4    ];
            a[2] = uX[(rb + g    ) * (STH/2) + kw + t4 + 4];
            a[3] = uX[(rb + g + 8) * (STH/2) + kw + t4 + 4];
            uint32_t b[8][2];
#pragma unroll
            for (int nf = 0; nf < 8; nf++) {
                b[nf][0] = uB[(nf * 8 + g) * (STH/2) + kw + t4    ];
                b[nf][1] = uB[(nf * 8 + g) * (STH/2) + kw + t4 + 4];
            }
#pragma unroll
            for (int nf = 0; nf < 8; nf++)
                MMA_F16_16x8x16(acc[nf], a, b[nf]);
        }

        if (tile < 7) {
            const int r0 = n0 + rb + g;
            const int r1 = r0 + 8;
#pragma unroll
            for (int nf = 0; nf < 8; nf++) {
                const int col = tile * 64 + nf * 8 + t4 * 2;
                if (r0 < N_PTS)
                    *(__half2*)(g_yh + (size_t)r0 * NCHP + col) =
                        __floats2half2_rn(acc[nf][0], acc[nf][1]);
                if (r1 < N_PTS)
                    *(__half2*)(g_yh + (size_t)r1 * NCHP + col) =
                        __floats2half2_rn(acc[nf][2], acc[nf][3]);
            }
        } else {
            const int cb = (tile - 7) * 64;
            const int rl0 = rb + g, rl1 = rl0 + 8;
            const int r0 = n0 + rl0, r1 = n0 + rl1;
#pragma unroll
            for (int nf = 0; nf < 8; nf++) {
                const int col = cb + nf * 8 + t4 * 2;
                const float gm0 = __ldg(v_gamma + col),     bt0 = __ldg(v_beta + col);
                const float gm1 = __ldg(v_gamma + col + 1), bt1 = __ldg(v_beta + col + 1);
                const int grp = col >> 3;
                if (r0 < N_PTS) {
                    const float pos = sPos[rl0 * 17 + grp];
                    const float o0 = fmaxf(fmaf(acc[nf][0], gm0, bt0), 0.f) + pos;
                    const float o1 = fmaxf(fmaf(acc[nf][1], gm1, bt1), 0.f) + pos;
                    *(__half2*)(g_vfh + (size_t)r0 * PLANES + col) = __floats2half2_rn(o0, o1);
                }
                if (r1 < N_PTS) {
                    const float pos = sPos[rl1 * 17 + grp];
                    const float o0 = fmaxf(fmaf(acc[nf][2], gm0, bt0), 0.f) + pos;
                    const float o1 = fmaxf(fmaf(acc[nf][3], gm1, bt1), 0.f) + pos;
                    *(__half2*)(g_vfh + (size_t)r1 * PLANES + col) = __floats2half2_rn(o0, o1);
                }
            }
        }
    }
}

// ---------------------------------------------------------------------------
// Kernel 2: 4 points per warp (8-lane groups). Gather fp16 y (32B = 1 sector
// per point-offset), then choice matvec partitioned c = h + 8j, group reduce.
// ---------------------------------------------------------------------------
__global__ __launch_bounds__(256) void k_qchoice(
    const float* __restrict__ q_gamma, const float* __restrict__ q_beta,
    const float* __restrict__ b_choice,
    const int* __restrict__ nbr_idx, const int* __restrict__ nbr_mask)
{
    __shared__ float sA[VEC * PLANES];
    __shared__ int sIdx[KOFF][32];
    __shared__ int sMsk[KOFF][32];

    const int tid = threadIdx.x, lane = tid & 31, wid = tid >> 5;
    const int nb0 = blockIdx.x * 32;

    for (int i = tid; i < VEC * PLANES / 4; i += 256)
        ((float4*)sA)[i] = __ldg((const float4*)g_A + i);
    for (int i = tid; i < KOFF * 32; i += 256) {
        const int k = i >> 5, p = i & 31;
        sIdx[k][p] = __ldg(nbr_idx  + k * N_PTS + nb0 + p);
        sMsk[k][p] = __ldg(nbr_mask + k * N_PTS + nb0 + p);
    }
    __syncthreads();

    const int g3 = lane >> 3, h = lane & 7;
    const int pl = wid * 4 + g3;              // local point 0..31

    float2 acc = make_float2(0.f, 0.f);
#pragma unroll
    for (int k = 0; k < KOFF; k++) {
        const int id = sIdx[k][pl];
        const int m  = sMsk[k][pl];
        if (m) {
            const __half2 t = __ldg((const __half2*)(g_yh + (size_t)id * NCHP + k * VEC) + h);
            const float2 f = __half22float2(t);
            acc.x += f.x; acc.y += f.y;
        }
    }
    float2 qf;
    qf.x = fmaxf(fmaf(acc.x, __ldg(q_gamma + 2*h    ), __ldg(q_beta + 2*h    )), 0.f);
    qf.y = fmaxf(fmaf(acc.y, __ldg(q_gamma + 2*h + 1), __ldg(q_beta + 2*h + 1)), 0.f);

    float qv[16];
#pragma unroll
    for (int hh = 0; hh < 8; hh++) {
        const int src = g3 * 8 + hh;
        qv[2*hh]     = __shfl_sync(0xffffffffu, qf.x, src);
        qv[2*hh + 1] = __shfl_sync(0xffffffffu, qf.y, src);
    }

    float tot = 0.f;
#pragma unroll
    for (int j = 0; j < 16; j++) {
        const int c = h + 8 * j;
        float s = __ldg(b_choice + c);
#pragma unroll
        for (int v = 0; v < VEC; v++)
            s = fmaf(qv[v], sA[v * PLANES + c], s);
        tot += fmaxf(s, 0.f);
    }
#pragma unroll
    for (int off = 4; off > 0; off >>= 1)
        tot += __shfl_xor_sync(0xffffffffu, tot, off);
    if (h == 0) g_choice[nb0 + pl] = tot;
}

// ---------------------------------------------------------------------------
// Kernel 2b: normalized attention weights. Warp per point, no smem.
// ---------------------------------------------------------------------------
__global__ __launch_bounds__(256) void k_attw(
    const int* __restrict__ nbr_idx, const int* __restrict__ nbr_mask)
{
    const int tid = threadIdx.x, lane = tid & 31, wid = tid >> 5;
    const int n = blockIdx.x * 8 + wid;    // grid = 12500 -> exactly N_PTS warps
    const float csum = g_csum;
    const float chn = __ldg(g_choice + n);

    int idxv = 0, mk = 0;
    if (lane < KOFF) {
        idxv = __ldg(nbr_idx  + lane * N_PTS + n);
        mk   = __ldg(nbr_mask + lane * N_PTS + n);
    }
    float s = (mk != 0) ? chn * __ldg(g_choice + idxv) * csum : -3.0e38f;
    float mx = s;
#pragma unroll
    for (int off = 16; off > 0; off >>= 1)
        mx = fmaxf(mx, __shfl_xor_sync(0xffffffffu, mx, off));
    const float e = (mk != 0) ? __expf(s - mx) : 0.f;
    float den = e;
#pragma unroll
    for (int off = 16; off > 0; off >>= 1)
        den += __shfl_xor_sync(0xffffffffu, den, off);
    if (lane < KOFF) g_aw[(size_t)n * 28 + lane] = e / den;
}

// ---------------------------------------------------------------------------
// Kernel 3 (256 thr): phase A: 8 warps x 16 points, gather fp16 v_f with
// precomputed weights into sAgg (fp16); phase B: fp16 mma out-projection.
// ---------------------------------------------------------------------------
#define AT_SMEM ((PLANES * STH + 64 * STH) * 2)

__global__ __launch_bounds__(256) void k_attn_out(
    const float* __restrict__ x,
    const float* __restrict__ out_gamma, const float* __restrict__ out_beta,
    const int* __restrict__ nbr_idx,
    float* __restrict__ out)
{
    extern __shared__ char smraw[];
    __half* sAgg = (__half*)smraw;                        // 128 * 136 halves
    __half* sBh  = (__half*)(smraw + PLANES * STH * 2);   // 64 * 136 halves

    const int tid = threadIdx.x;
    const int wid = tid >> 5, lane = tid & 31;
    const int g   = lane >> 2, t4 = lane & 3;
    const int n0  = blockIdx.x * 128;
    const int rb  = wid * 16;

    // ---- phase A: each warp aggregates 16 points
#pragma unroll 1
    for (int pp = 0; pp < 16; pp++) {
        const int pl = wid * 16 + pp;
        const int n  = n0 + pl;
        if (n >= N_PTS) {
            *(uint2*)&sAgg[pl * STH + lane * 4] = make_uint2(0u, 0u);
            continue;
        }
        float wkf = 0.f;
        int idxv = 0;
        if (lane < KOFF) {
            wkf  = __ldg(g_aw + (size_t)n * 28 + lane);
            idxv = __ldg(nbr_idx + lane * N_PTS + n);
        }

        float ax = 0.f, ay = 0.f, az = 0.f, aw2 = 0.f;
#pragma unroll
        for (int k0 = 0; k0 < KOFF; k0 += 9) {
            float wk[9]; int ik[9];
#pragma unroll
            for (int q = 0; q < 9; q++) {
                wk[q] = __shfl_sync(0xffffffffu, wkf,  k0 + q);
                ik[q] = __shfl_sync(0xffffffffu, idxv, k0 + q);
            }
            uint2 t[9];
#pragma unroll
            for (int q = 0; q < 9; q++) {
                t[q] = make_uint2(0u, 0u);
                if (wk[q] != 0.f)
                    t[q] = __ldg((const uint2*)(g_vfh + (size_t)ik[q] * PLANES) + lane);
            }
#pragma unroll
            for (int q = 0; q < 9; q++) {
                const float2 fa = __half22float2(*(__half2*)&t[q].x);
                const float2 fb = __half22float2(*(__half2*)&t[q].y);
                ax  = fmaf(wk[q], fa.x, ax);
                ay  = fmaf(wk[q], fa.y, ay);
                az  = fmaf(wk[q], fb.x, az);
                aw2 = fmaf(wk[q], fb.y, aw2);
            }
        }
        __half2 h0 = __floats2half2_rn(ax, ay);
        __half2 h1 = __floats2half2_rn(az, aw2);
        *(uint2*)&sAgg[pl * STH + lane * 4] = make_uint2(*(uint32_t*)&h0, *(uint32_t*)&h1);
    }

    // ---- phase B: 128x128 @ 128x128 fp16 mma GEMM (2 N-tiles of 64)
    const uint32_t* uX = (const uint32_t*)sAgg;
    const uint32_t* uB = (const uint32_t*)sBh;

    for (int tile = 0; tile < 2; tile++) {
        __syncthreads();
        for (int it = 0; it < 4; it++) {
            const int id = it * 256 + tid;
            const int r = id >> 4, c16 = id & 15;
            *(uint4*)&sBh[r * STH + c16 * 8] =
                __ldg((const uint4*)(g_Wth + (size_t)(NCHP + PLANES + tile * 64 + r) * PLANES) + c16);
        }
        __syncthreads();

        float acc[8][4];
#pragma unroll
        for (int nf = 0; nf < 8; nf++)
#pragma unroll
            for (int q = 0; q < 4; q++) acc[nf][q] = 0.f;

#pragma unroll 2
        for (int kb = 0; kb < 8; kb++) {
            const int kw = kb * 8;
            uint32_t a[4];
            a[0] = uX[(rb + g    ) * (STH/2) + kw + t4    ];
            a[1] = uX[(rb + g + 8) * (STH/2) + kw + t4    ];
            a[2] = uX[(rb + g    ) * (STH/2) + kw + t4 + 4];
            a[3] = uX[(rb + g + 8) * (STH/2) + kw + t4 + 4];
            uint32_t b[8][2];
#pragma unroll
            for (int nf = 0; nf < 8; nf++) {
                b[nf][0] = uB[(nf * 8 + g) * (STH/2) + kw + t4    ];
                b[nf][1] = uB[(nf * 8 + g) * (STH/2) + kw + t4 + 4];
            }
#pragma unroll
            for (int nf = 0; nf < 8; nf++)
                MMA_F16_16x8x16(acc[nf], a, b[nf]);
        }

        const int r0 = n0 + rb + g;
        const int r1 = r0 + 8;
#pragma unroll
        for (int nf = 0; nf < 8; nf++) {
            const int col = tile * 64 + nf * 8 + t4 * 2;
            const float gm0 = __ldg(out_gamma + col),     bt0 = __ldg(out_beta + col);
            const float gm1 = __ldg(out_gamma + col + 1), bt1 = __ldg(out_beta + col + 1);
            if (r0 < N_PTS) {
                const float2 xv = __ldg((const float2*)(x + (size_t)r0 * PLANES + col));
                const float o0 = fmaxf(fmaf(acc[nf][0], gm0, bt0), 0.f) + xv.x;
                const float o1 = fmaxf(fmaf(acc[nf][1], gm1, bt1), 0.f) + xv.y;
                *(float2*)(out + (size_t)r0 * PLANES + col) = make_float2(o0, o1);
            }
            if (r1 < N_PTS) {
                const float2 xv = __ldg((const float2*)(x + (size_t)r1 * PLANES + col));
                const float o0 = fmaxf(fmaf(acc[nf][2], gm0, bt0), 0.f) + xv.x;
                const float o1 = fmaxf(fmaf(acc[nf][3], gm1, bt1), 0.f) + xv.y;
                *(float2*)(out + (size_t)r1 * PLANES + col) = make_float2(o0, o1);
            }
        }
    }
}

// ---------------------------------------------------------------------------
extern "C" void kernel_launch(void* const* d_in, const int* in_sizes, int n_in,
                              void* d_out, int out_size)
{
    const float* x         = (const float*)d_in[0];
    const float* coords    = (const float*)d_in[1];
    const float* W_q       = (const float*)d_in[2];
    const float* q_gamma   = (const float*)d_in[3];
    const float* q_beta    = (const float*)d_in[4];
    const float* W_v       = (const float*)d_in[5];
    const float* v_gamma   = (const float*)d_in[6];
    const float* v_beta    = (const float*)d_in[7];
    const float* codebook  = (const float*)d_in[8];
    const float* W_choice  = (const float*)d_in[9];
    const float* b_choice  = (const float*)d_in[10];
    const float* W_pos     = (const float*)d_in[11];
    const float* b_pos     = (const float*)d_in[12];
    const float* W_out     = (const float*)d_in[13];
    const float* out_gamma = (const float*)d_in[14];
    const float* out_beta  = (const float*)d_in[15];
    const int*   nbr_idx   = (const int*)d_in[16];
    const int*   nbr_mask  = (const int*)d_in[17];
    float* out = (float*)d_out;

    cudaFuncSetAttribute(k_gemm1,    cudaFuncAttributeMaxDynamicSharedMemorySize, G1_SMEM);
    cudaFuncSetAttribute(k_attn_out, cudaFuncAttributeMaxDynamicSharedMemorySize, AT_SMEM);

    const int nblk = (N_PTS + 127) / 128;   // 782
    k_prep<<<1, 128>>>(codebook, W_choice);
    k_prepW<<<NCOLS, 128>>>(W_q, W_v, W_out);
    k_gemm1<<<nblk, 256, G1_SMEM>>>(x, coords, W_pos, b_pos, v_gamma, v_beta);
    k_qchoice<<<N_PTS / 32, 256>>>(q_gamma, q_beta, b_choice, nbr_idx, nbr_mask);
    k_attw<<<N_PTS / 8, 256>>>(nbr_idx, nbr_mask);
    k_attn_out<<<nblk, 256, AT_SMEM>>>(x, out_gamma, out_beta, nbr_idx, out);
}